// round 6
// baseline (speedup 1.0000x reference)
#include <cuda_runtime.h>
#include <cuda_bf16.h>

#define NN 50000
#define EE 800000
#define DD 128
#define NH 8
#define TE2 128          // edges per tile (persistent kernels)
#define NT 6250          // EE / TE2
#define SA 168           // s_A row stride (bf16) -> LDSM conflict-free
#define WS2 136          // weight row stride (bf16) -> LDSM conflict-free
#define SSH 24           // s_sh row stride
#define XS 136           // s_xw row stride
#define NTHR 512

// ---------------- scratch (static __device__) ----------------
__device__ float    g_a[(size_t)EE * NH];
__device__ float    g_agg[(size_t)NN * DD];
__device__ unsigned g_maxbits[NH];
__device__ float    g_sum[NH];

__device__ __forceinline__ float siluf(float x) { return x / (1.f + __expf(-x)); }
__device__ __forceinline__ unsigned encf(float x) {
    unsigned u = __float_as_uint(x);
    return (u & 0x80000000u) ? ~u : (u | 0x80000000u);
}
__device__ __forceinline__ float decf(unsigned u) {
    return __uint_as_float((u & 0x80000000u) ? (u ^ 0x80000000u) : ~u);
}
__device__ __forceinline__ void ldsm4(unsigned (&r)[4], unsigned addr) {
    asm volatile("ldmatrix.sync.aligned.m8n8.x4.shared.b16 {%0,%1,%2,%3}, [%4];"
                 : "=r"(r[0]), "=r"(r[1]), "=r"(r[2]), "=r"(r[3]) : "r"(addr));
}
__device__ __forceinline__ void ldsm4t(unsigned* r, unsigned addr) {
    asm volatile("ldmatrix.sync.aligned.m8n8.x4.trans.shared.b16 {%0,%1,%2,%3}, [%4];"
                 : "=r"(r[0]), "=r"(r[1]), "=r"(r[2]), "=r"(r[3]) : "r"(addr));
}
__device__ __forceinline__ void mma16(float (&d)[4], const unsigned (&a)[4],
                                      unsigned b0, unsigned b1) {
    asm volatile(
        "mma.sync.aligned.m16n8k16.row.col.f32.bf16.bf16.f32 "
        "{%0,%1,%2,%3}, {%4,%5,%6,%7}, {%8,%9}, {%0,%1,%2,%3};\n"
        : "+f"(d[0]), "+f"(d[1]), "+f"(d[2]), "+f"(d[3])
        : "r"(a[0]), "r"(a[1]), "r"(a[2]), "r"(a[3]), "r"(b0), "r"(b1));
}

// stage a [rows x 128] fp32 weight matrix into resident bf16 shared (stride WS2)
__device__ __forceinline__ void stageW(const float* __restrict__ W,
                                       __nv_bfloat16* sW, int rows, int tid)
{
    for (int idx = tid; idx < rows * 32; idx += NTHR) {
        int rr = idx >> 5, cc = (idx & 31) << 2;
        const float4 w4 = *(const float4*)(W + (size_t)rr * DD + cc);
        *(__nv_bfloat162*)(sW + rr * WS2 + cc)     = __floats2bfloat162_rn(w4.x, w4.y);
        *(__nv_bfloat162*)(sW + rr * WS2 + cc + 2) = __floats2bfloat162_rn(w4.z, w4.w);
    }
}

// ---------------- bf16 warp-tiled GEMM, weights RESIDENT in shared ----------------
// 512 threads = 16 warps. Warp w: rows (w&7)*16..+15, cols (w>>3)*64..+63.
// No internal syncs: sW is immutable, sA guarded by caller.
template<int K>
__device__ __forceinline__ void bgemm_r(const __nv_bfloat16* sW,
        const __nv_bfloat16* sA, int lda, float (&acc)[8][4],
        int lrow, int lcol8, int mr0, int nc0, bool clear)
{
    if (clear) {
#pragma unroll
        for (int i = 0; i < 8; i++)
#pragma unroll
            for (int j = 0; j < 4; j++) acc[i][j] = 0.f;
    }
#pragma unroll
    for (int k0 = 0; k0 < K; k0 += 16) {
        unsigned a[4];
        ldsm4(a, (unsigned)__cvta_generic_to_shared(
                     sA + (mr0 + lrow) * lda + k0 + lcol8));
        unsigned b[16];
#pragma unroll
        for (int np = 0; np < 4; np++)
            ldsm4t(b + np * 4, (unsigned)__cvta_generic_to_shared(
                       sW + (k0 + lrow) * WS2 + nc0 + np * 16 + lcol8));
#pragma unroll
        for (int nt = 0; nt < 8; nt++)
            mma16(acc[nt], a, b[(nt >> 1) * 4 + (nt & 1) * 2],
                              b[(nt >> 1) * 4 + (nt & 1) * 2 + 1]);
    }
}

// bias + silu on C-fragments -> bf16 s_A (frag-owned slots)
__device__ __forceinline__ void epi_silu(const float (&acc)[8][4], const float* sb,
                                         __nv_bfloat16* s_A, int r, int c,
                                         int mr0, int nc0)
{
#pragma unroll
    for (int nt = 0; nt < 8; nt++) {
        int col = nc0 + nt * 8 + 2 * c;
        float b0 = sb[col], b1 = sb[col + 1];
        *(__nv_bfloat162*)(s_A + (mr0 + r) * SA + col) =
            __floats2bfloat162_rn(siluf(acc[nt][0] + b0), siluf(acc[nt][1] + b1));
        *(__nv_bfloat162*)(s_A + (mr0 + r + 8) * SA + col) =
            __floats2bfloat162_rn(siluf(acc[nt][2] + b0), siluf(acc[nt][3] + b1));
    }
}

// ---------------- K0: init ----------------
__global__ void k_init()
{
    int i = blockIdx.x * blockDim.x + threadIdx.x;
    int stride = gridDim.x * blockDim.x;
    for (int j = i; j < NN * DD; j += stride) g_agg[j] = 0.f;
    if (i < NH) { g_maxbits[i] = 0u; g_sum[i] = 0.f; }
}

// ---------------- K1: persistent attention kernel ----------------
// smem: s_A 43008 | weights 78336 (aW1 rows 0-159, aW2 rows 160-287) | aW3 f32 4096 |
//       bias 1024 | src 512 | dst 512 | maxb 32  => 127520 B
__global__ void __launch_bounds__(NTHR, 1)
k_att(const float* __restrict__ nf, const float* __restrict__ edge_attr,
      const float* __restrict__ aW1, const float* __restrict__ ab1,
      const float* __restrict__ aW2, const float* __restrict__ ab2,
      const float* __restrict__ aW3, const float* __restrict__ ab3,
      const int* __restrict__ edge_index)
{
    extern __shared__ char smem[];
    __nv_bfloat16* s_A   = (__nv_bfloat16*)smem;                  // 43008
    __nv_bfloat16* s_wts = (__nv_bfloat16*)(smem + 43008);        // 78336
    float*    s_aW3  = (float*)(smem + 121344);                   // 4096
    float*    s_bias = (float*)(smem + 125440);                   // 1024
    int*      s_src  = (int*)(smem + 126464);                     // 512
    int*      s_dst  = (int*)(smem + 126976);                     // 512
    unsigned* s_maxb = (unsigned*)(smem + 127488);                // 32

    const int tid = threadIdx.x, lane = tid & 31, wid = tid >> 5;
    const int r = lane >> 2, c = lane & 3;
    const int lrow = lane & 15, lcol8 = (lane >> 1) & 8;
    const int mr0 = (wid & 7) * 16, nc0 = (wid >> 3) * 64;

    stageW(aW1, s_wts, 160, tid);
    stageW(aW2, s_wts + 160 * WS2, 128, tid);
    if (tid < 256) *(float4*)(s_aW3 + tid * 4) = *(const float4*)(aW3 + tid * 4);
    if (tid < 128) {
        s_bias[tid]       = ab1[tid];
        s_bias[128 + tid] = ab2[tid];
    }
    if (tid < NH) s_maxb[tid] = 0u;

    float acc[8][4];
    for (int t = blockIdx.x; t < NT; t += gridDim.x) {
        const int e0 = t * TE2;
        __syncthreads();   // protect smem reuse from previous tile
        if (tid < TE2) {
            s_src[tid] = edge_index[e0 + tid];
            s_dst[tid] = edge_index[EE + e0 + tid];
        }
        // edge_attr -> s_A cols [128,160)
        for (int idx = tid; idx < TE2 * 8; idx += NTHR) {
            int rr = idx >> 3, cc = (idx & 7) << 2;
            const float4 v = *(const float4*)(edge_attr + (size_t)(e0 + rr) * 32 + cc);
            *(__nv_bfloat162*)(s_A + rr * SA + 128 + cc)     = __floats2bfloat162_rn(v.x, v.y);
            *(__nv_bfloat162*)(s_A + rr * SA + 128 + cc + 2) = __floats2bfloat162_rn(v.z, v.w);
        }
        __syncthreads();
        // x_src[:64] -> cols [0,64), x_dst[:64] -> cols [64,128)  (warp-private rows)
#pragma unroll
        for (int i = 0; i < 8; i++) {
            int rr = wid * 8 + i;
            const float2 vs = *(const float2*)(nf + (size_t)s_src[rr] * DD + lane * 2);
            const float2 vd = *(const float2*)(nf + (size_t)s_dst[rr] * DD + lane * 2);
            *(__nv_bfloat162*)(s_A + rr * SA + lane * 2)      = __floats2bfloat162_rn(vs.x, vs.y);
            *(__nv_bfloat162*)(s_A + rr * SA + 64 + lane * 2) = __floats2bfloat162_rn(vd.x, vd.y);
        }
        __syncthreads();

        bgemm_r<160>(s_wts, s_A, SA, acc, lrow, lcol8, mr0, nc0, true);
        __syncthreads();
        epi_silu(acc, s_bias, s_A, r, c, mr0, nc0);
        __syncthreads();

        bgemm_r<128>(s_wts + 160 * WS2, s_A, SA, acc, lrow, lcol8, mr0, nc0, true);
        __syncthreads();
        epi_silu(acc, s_bias + 128, s_A, r, c, mr0, nc0);
        __syncthreads();

        if (tid < TE2) {
            float av[NH];
#pragma unroll
            for (int h = 0; h < NH; h++) av[h] = ab3[h];
            for (int k = 0; k < 128; k++) {
                float x = __bfloat162float(s_A[tid * SA + k]);
#pragma unroll
                for (int h = 0; h < NH; h++) av[h] += x * s_aW3[k * 8 + h];
            }
            float4* gp = (float4*)(g_a + (size_t)(e0 + tid) * NH);
            gp[0] = make_float4(av[0], av[1], av[2], av[3]);
            gp[1] = make_float4(av[4], av[5], av[6], av[7]);
#pragma unroll
            for (int h = 0; h < NH; h++) atomicMax(&s_maxb[h], encf(av[h]));
        }
    }
    __syncthreads();
    if (tid < NH) atomicMax(&g_maxbits[tid], s_maxb[tid]);
}

// ---------------- K2: per-head sum of exp(a - max) ----------------
__global__ void k_sumexp()
{
    __shared__ float s_sum[NH];
    if (threadIdx.x < NH) s_sum[threadIdx.x] = 0.f;
    __syncthreads();
    float mx[NH];
#pragma unroll
    for (int h = 0; h < NH; h++) mx[h] = decf(g_maxbits[h]);
    float loc[NH];
#pragma unroll
    for (int h = 0; h < NH; h++) loc[h] = 0.f;
    for (int e = blockIdx.x * blockDim.x + threadIdx.x; e < EE; e += gridDim.x * blockDim.x) {
        const float4 a0 = *(const float4*)(g_a + (size_t)e * NH);
        const float4 a1 = *(const float4*)(g_a + (size_t)e * NH + 4);
        loc[0] += __expf(a0.x - mx[0]); loc[1] += __expf(a0.y - mx[1]);
        loc[2] += __expf(a0.z - mx[2]); loc[3] += __expf(a0.w - mx[3]);
        loc[4] += __expf(a1.x - mx[4]); loc[5] += __expf(a1.y - mx[5]);
        loc[6] += __expf(a1.z - mx[6]); loc[7] += __expf(a1.w - mx[7]);
    }
#pragma unroll
    for (int h = 0; h < NH; h++) atomicAdd(&s_sum[h], loc[h]);
    __syncthreads();
    if (threadIdx.x < NH) atomicAdd(&g_sum[threadIdx.x], s_sum[threadIdx.x]);
}

// ---------------- K3: persistent message kernel (fused weighted scatter) ----------------
// smem: s_A 43008 | s_xw 34816 | s_sh 6144 | weights 117504
//       (W_node rows 0-127, fc1 128-159, fc2 160-287, fc3 288-415, W_sh 416-431)
//       | bias 1536 | wt 512 | src 512 | dst 512  => 204544 B
__global__ void __launch_bounds__(NTHR, 1)
k_msg(const float* __restrict__ nf, const float* __restrict__ edge_attr,
      const float* __restrict__ edge_sh,
      const float* __restrict__ W_node,
      const float* __restrict__ fc1, const float* __restrict__ b1,
      const float* __restrict__ fc2, const float* __restrict__ b2,
      const float* __restrict__ fc3, const float* __restrict__ b3,
      const float* __restrict__ W_sh,
      const int* __restrict__ edge_index)
{
    extern __shared__ char smem[];
    __nv_bfloat16* s_A   = (__nv_bfloat16*)smem;                  // 43008
    __nv_bfloat16* s_xw  = (__nv_bfloat16*)(smem + 43008);        // 34816
    __nv_bfloat16* s_sh  = (__nv_bfloat16*)(smem + 77824);        // 6144
    __nv_bfloat16* s_wts = (__nv_bfloat16*)(smem + 83968);        // 117504
    float* s_bias = (float*)(smem + 201472);                      // 1536
    float* s_wt   = (float*)(smem + 203008);                      // 512
    int*   s_src  = (int*)(smem + 203520);                        // 512
    int*   s_dst  = (int*)(smem + 204032);                        // 512

    const int tid = threadIdx.x, lane = tid & 31, wid = tid >> 5;
    const int r = lane >> 2, c = lane & 3;
    const int lrow = lane & 15, lcol8 = (lane >> 1) & 8;
    const int mr0 = (wid & 7) * 16, nc0 = (wid >> 3) * 64;

    stageW(W_node, s_wts,             128, tid);
    stageW(fc1,    s_wts + 128 * WS2,  32, tid);
    stageW(fc2,    s_wts + 160 * WS2, 128, tid);
    stageW(fc3,    s_wts + 288 * WS2, 128, tid);
    stageW(W_sh,   s_wts + 416 * WS2,  16, tid);
    if (tid < 128) {
        s_bias[tid]       = b1[tid];
        s_bias[128 + tid] = b2[tid];
        s_bias[256 + tid] = b3[tid];
    }
    float mxh[NH], ish[NH];
#pragma unroll
    for (int h = 0; h < NH; h++) mxh[h] = decf(g_maxbits[h]);
#pragma unroll
    for (int h = 0; h < NH; h++) ish[h] = 1.f / g_sum[h];

    float acc[8][4];
    for (int t = blockIdx.x; t < NT; t += gridDim.x) {
        const int e0 = t * TE2;
        __syncthreads();   // protect smem reuse from previous tile
        if (tid < TE2) {
            s_src[tid] = edge_index[e0 + tid];
            s_dst[tid] = edge_index[EE + e0 + tid];
        }
        if (tid < TE2) {   // per-edge softmax-mean weight
            int e = e0 + tid;
            float w = 0.f;
#pragma unroll
            for (int h = 0; h < NH; h++)
                w += __expf(g_a[(size_t)e * NH + h] - mxh[h]) * ish[h];
            s_wt[tid] = w * 0.125f;
        }
        for (int idx = tid; idx < TE2 * 4; idx += NTHR) {   // edge_sh [128][16]
            int rr = idx >> 2, cc = (idx & 3) << 2;
            const float4 v = *(const float4*)(edge_sh + (size_t)(e0 + rr) * 16 + cc);
            *(__nv_bfloat162*)(s_sh + rr * SSH + cc)     = __floats2bfloat162_rn(v.x, v.y);
            *(__nv_bfloat162*)(s_sh + rr * SSH + cc + 2) = __floats2bfloat162_rn(v.z, v.w);
        }
        __syncthreads();
        // full x_src rows (warp-private)
#pragma unroll
        for (int i = 0; i < 8; i++) {
            int rr = wid * 8 + i;
            const float4 v = *(const float4*)(nf + (size_t)s_src[rr] * DD + lane * 4);
            *(__nv_bfloat162*)(s_A + rr * SA + lane * 4)     = __floats2bfloat162_rn(v.x, v.y);
            *(__nv_bfloat162*)(s_A + rr * SA + lane * 4 + 2) = __floats2bfloat162_rn(v.z, v.w);
        }
        __syncthreads();

        // 1) xw = x_src @ W_node -> s_xw (frag-owned slots)
        bgemm_r<128>(s_wts, s_A, SA, acc, lrow, lcol8, mr0, nc0, true);
#pragma unroll
        for (int nt = 0; nt < 8; nt++) {
            int col = nc0 + nt * 8 + 2 * c;
            *(__nv_bfloat162*)(s_xw + (mr0 + r) * XS + col) =
                __floats2bfloat162_rn(acc[nt][0], acc[nt][1]);
            *(__nv_bfloat162*)(s_xw + (mr0 + r + 8) * XS + col) =
                __floats2bfloat162_rn(acc[nt][2], acc[nt][3]);
        }
        __syncthreads();

        // 2) edge_attr -> s_A cols [0,32)
        for (int idx = tid; idx < TE2 * 8; idx += NTHR) {
            int rr = idx >> 3, cc = (idx & 7) << 2;
            const float4 v = *(const float4*)(edge_attr + (size_t)(e0 + rr) * 32 + cc);
            *(__nv_bfloat162*)(s_A + rr * SA + cc)     = __floats2bfloat162_rn(v.x, v.y);
            *(__nv_bfloat162*)(s_A + rr * SA + cc + 2) = __floats2bfloat162_rn(v.z, v.w);
        }
        __syncthreads();

        // 3) radial MLP
        bgemm_r<32>(s_wts + 128 * WS2, s_A, SA, acc, lrow, lcol8, mr0, nc0, true);
        __syncthreads();
        epi_silu(acc, s_bias, s_A, r, c, mr0, nc0);
        __syncthreads();

        bgemm_r<128>(s_wts + 160 * WS2, s_A, SA, acc, lrow, lcol8, mr0, nc0, true);
        __syncthreads();
        epi_silu(acc, s_bias + 128, s_A, r, c, mr0, nc0);
        __syncthreads();

        bgemm_r<128>(s_wts + 288 * WS2, s_A, SA, acc, lrow, lcol8, mr0, nc0, true);
        __syncthreads();
        // 4) scale = fc3 + b3 -> s_A (frag-owned slots)
#pragma unroll
        for (int nt = 0; nt < 8; nt++) {
            int col = nc0 + nt * 8 + 2 * c;
            float b0 = s_bias[256 + col], b1v = s_bias[256 + col + 1];
            *(__nv_bfloat162*)(s_A + (mr0 + r) * SA + col) =
                __floats2bfloat162_rn(acc[nt][0] + b0, acc[nt][1] + b1v);
            *(__nv_bfloat162*)(s_A + (mr0 + r + 8) * SA + col) =
                __floats2bfloat162_rn(acc[nt][2] + b0, acc[nt][3] + b1v);
        }

        // 5) shp = edge_sh @ W_sh (reads only s_sh, untouched)
        bgemm_r<16>(s_wts + 416 * WS2, s_sh, SSH, acc, lrow, lcol8, mr0, nc0, true);

        // 6) msg = silu(xw * scale + shp) * wt -> s_xw (all frag-owned reads/writes)
#pragma unroll
        for (int nt = 0; nt < 8; nt++) {
            int col = nc0 + nt * 8 + 2 * c;
            float w0 = s_wt[mr0 + r], w1 = s_wt[mr0 + r + 8];
            float2 sc0 = __bfloat1622float2(*(__nv_bfloat162*)(s_A + (mr0 + r) * SA + col));
            float2 sc1 = __bfloat1622float2(*(__nv_bfloat162*)(s_A + (mr0 + r + 8) * SA + col));
            float2 xw0 = __bfloat1622float2(*(__nv_bfloat162*)(s_xw + (mr0 + r) * XS + col));
            float2 xw1 = __bfloat1622float2(*(__nv_bfloat162*)(s_xw + (mr0 + r + 8) * XS + col));
            *(__nv_bfloat162*)(s_xw + (mr0 + r) * XS + col) = __floats2bfloat162_rn(
                siluf(xw0.x * sc0.x + acc[nt][0]) * w0, siluf(xw0.y * sc0.y + acc[nt][1]) * w0);
            *(__nv_bfloat162*)(s_xw + (mr0 + r + 8) * XS + col) = __floats2bfloat162_rn(
                siluf(xw1.x * sc1.x + acc[nt][2]) * w1, siluf(xw1.y * sc1.y + acc[nt][3]) * w1);
        }
        __syncthreads();

        // 7) coalesced scatter: warp handles 8 rows, lane covers 4 cols
#pragma unroll
        for (int i = 0; i < 8; i++) {
            int rr = wid * 8 + i;
            int d = s_dst[rr];
            __nv_bfloat162 p0 = *(__nv_bfloat162*)(s_xw + rr * XS + lane * 4);
            __nv_bfloat162 p1 = *(__nv_bfloat162*)(s_xw + rr * XS + lane * 4 + 2);
            float2 f0 = __bfloat1622float2(p0), f1 = __bfloat1622float2(p1);
            float* p = g_agg + (size_t)d * DD + lane * 4;
            atomicAdd(p + 0, f0.x);
            atomicAdd(p + 1, f0.y);
            atomicAdd(p + 2, f1.x);
            atomicAdd(p + 3, f1.y);
        }
    }
}

// ---------------- K4: out = LN(nf + agg @ W_out) ----------------
__global__ void k_node(const float* __restrict__ nf, const float* __restrict__ W_out,
                       float* __restrict__ out)
{
    extern __shared__ float smemf[];
    float* sW    = smemf;             // 128*128
    float* s_row = sW + 128 * 128;    // 8*128
    const int tid = threadIdx.x, tx = tid & 31, w = tid >> 5;
    for (int idx = tid; idx < 128 * 32; idx += 256) {
        int rr = idx >> 5, cc = (idx & 31) << 2;
        *(float4*)(sW + rr * 128 + cc) = *(const float4*)(W_out + (size_t)rr * 128 + cc);
    }
    __syncthreads();
    for (int n = blockIdx.x * 8 + w; n < NN; n += gridDim.x * 8) {
        float4 av = *(const float4*)(g_agg + (size_t)n * DD + tx * 4);
        __syncwarp();
        *(float4*)(s_row + w * 128 + tx * 4) = av;
        __syncwarp();
        float a0 = 0.f, a1 = 0.f, a2 = 0.f, a3 = 0.f;
#pragma unroll 8
        for (int k = 0; k < 128; k++) {
            float a = s_row[w * 128 + k];
            const float4 wv = *(const float4*)(sW + k * 128 + tx * 4);
            a0 += a * wv.x; a1 += a * wv.y; a2 += a * wv.z; a3 += a * wv.w;
        }
        const float4 x = *(const float4*)(nf + (size_t)n * DD + tx * 4);
        float v0 = x.x + a0, v1 = x.y + a1, v2 = x.z + a2, v3 = x.w + a3;
        float s = v0 + v1 + v2 + v3;
#pragma unroll
        for (int o = 16; o > 0; o >>= 1) s += __shfl_xor_sync(0xffffffffu, s, o);
        float mu = s * (1.f / 128.f);
        float d0 = v0 - mu, d1 = v1 - mu, d2 = v2 - mu, d3 = v3 - mu;
        float q = d0 * d0 + d1 * d1 + d2 * d2 + d3 * d3;
#pragma unroll
        for (int o = 16; o > 0; o >>= 1) q += __shfl_xor_sync(0xffffffffu, q, o);
        float rs = rsqrtf(q * (1.f / 128.f) + 1e-5f);
        float4 o4 = make_float4(d0 * rs, d1 * rs, d2 * rs, d3 * rs);
        *(float4*)(out + (size_t)n * DD + tx * 4) = o4;
    }
}

// ---------------- host launcher ----------------
extern "C" void kernel_launch(void* const* d_in, const int* in_sizes, int n_in,
                              void* d_out, int out_size)
{
    const float* nf        = (const float*)d_in[0];
    const float* edge_attr = (const float*)d_in[1];
    const float* edge_sh   = (const float*)d_in[2];
    const float* W_node    = (const float*)d_in[3];
    const float* fc1 = (const float*)d_in[4];
    const float* b1  = (const float*)d_in[5];
    const float* fc2 = (const float*)d_in[6];
    const float* b2  = (const float*)d_in[7];
    const float* fc3 = (const float*)d_in[8];
    const float* b3  = (const float*)d_in[9];
    const float* W_sh = (const float*)d_in[10];
    const float* aW1 = (const float*)d_in[11];
    const float* ab1 = (const float*)d_in[12];
    const float* aW2 = (const float*)d_in[13];
    const float* ab2 = (const float*)d_in[14];
    const float* aW3 = (const float*)d_in[15];
    const float* ab3 = (const float*)d_in[16];
    const float* W_out = (const float*)d_in[17];
    const int* edge_index = (const int*)d_in[18];
    float* out = (float*)d_out;

    const int SMEM_ATT  = 127520;
    const int SMEM_MSG  = 204544;
    const int SMEM_NODE = (128 * 128 + 8 * 128) * 4;
    cudaFuncSetAttribute(k_att,  cudaFuncAttributeMaxDynamicSharedMemorySize, SMEM_ATT);
    cudaFuncSetAttribute(k_msg,  cudaFuncAttributeMaxDynamicSharedMemorySize, SMEM_MSG);
    cudaFuncSetAttribute(k_node, cudaFuncAttributeMaxDynamicSharedMemorySize, SMEM_NODE);

    k_init<<<2048, 256>>>();
    k_att<<<148, NTHR, SMEM_ATT>>>(nf, edge_attr, aW1, ab1, aW2, ab2, aW3, ab3, edge_index);
    k_sumexp<<<1024, 256>>>();
    k_msg<<<148, NTHR, SMEM_MSG>>>(nf, edge_attr, edge_sh, W_node,
                                   fc1, b1, fc2, b2, fc3, b3, W_sh, edge_index);
    k_node<<<296, 256, SMEM_NODE>>>(nf, W_out, out);
}

// round 7
// speedup vs baseline: 2.0924x; 2.0924x over previous
#include <cuda_runtime.h>
#include <cuda_bf16.h>

#define NN 50000
#define EE 800000
#define DD 128
#define NH 8
#define TE 64
#define SA 168
#define WS2 136
#define SSH 24
#define SEA 40
#define XS 136
#define CHUNKW (32 * WS2)

__device__ float    g_a[(size_t)EE * NH];
__device__ float    g_agg[(size_t)NN * DD];
__device__ unsigned g_maxbits[NH];
__device__ float    g_sum[NH];
__device__ __align__(256) __nv_bfloat16 g_watt[288 * 128];
__device__ __align__(256) __nv_bfloat16 g_wmsg[432 * 128];

__device__ __forceinline__ float siluf(float x) { return x / (1.f + __expf(-x)); }
__device__ __forceinline__ unsigned encf(float x) {
    unsigned u = __float_as_uint(x);
    return (u & 0x80000000u) ? ~u : (u | 0x80000000u);
}
__device__ __forceinline__ float decf(unsigned u) {
    return __uint_as_float((u & 0x80000000u) ? (u ^ 0x80000000u) : ~u);
}
__device__ __forceinline__ void ldsm4(unsigned (&r)[4], unsigned addr) {
    asm volatile("ldmatrix.sync.aligned.m8n8.x4.shared.b16 {%0,%1,%2,%3}, [%4];"
                 : "=r"(r[0]), "=r"(r[1]), "=r"(r[2]), "=r"(r[3]) : "r"(addr));
}
__device__ __forceinline__ void ldsm4t(unsigned* r, unsigned addr) {
    asm volatile("ldmatrix.sync.aligned.m8n8.x4.trans.shared.b16 {%0,%1,%2,%3}, [%4];"
                 : "=r"(r[0]), "=r"(r[1]), "=r"(r[2]), "=r"(r[3]) : "r"(addr));
}
__device__ __forceinline__ void mma16(float (&d)[4], const unsigned (&a)[4],
                                      unsigned b0, unsigned b1) {
    asm volatile(
        "mma.sync.aligned.m16n8k16.row.col.f32.bf16.bf16.f32 "
        "{%0,%1,%2,%3}, {%4,%5,%6,%7}, {%8,%9}, {%0,%1,%2,%3};\n"
        : "+f"(d[0]), "+f"(d[1]), "+f"(d[2]), "+f"(d[3])
        : "r"(a[0]), "r"(a[1]), "r"(a[2]), "r"(a[3]), "r"(b0), "r"(b1));
}
__device__ __forceinline__ void clr(float (&acc)[8][4]) {
#pragma unroll
    for (int i = 0; i < 8; i++)
#pragma unroll
        for (int j = 0; j < 4; j++) acc[i][j] = 0.f;
}

__device__ __forceinline__ void prefetch_chunk(__nv_bfloat16* sbuf,
        const __nv_bfloat16* __restrict__ gsrc, int nrows, int tid)
{
    for (int idx = tid; idx < nrows * 16; idx += 256) {
        int row = idx >> 4, seg = idx & 15;
        unsigned d = (unsigned)__cvta_generic_to_shared(sbuf + row * WS2) + seg * 16;
        const char* s = (const char*)(gsrc + (size_t)row * 128) + seg * 16;
        asm volatile("cp.async.cg.shared.global [%0], [%1], 16;" :: "r"(d), "l"(s));
    }
    asm volatile("cp.async.commit_group;" ::: "memory");
}
__device__ __forceinline__ void commit_empty() {
    asm volatile("cp.async.commit_group;" ::: "memory");
}
__device__ __forceinline__ void wait1() {
    asm volatile("cp.async.wait_group 1;" ::: "memory");
}

template<int NK>
__device__ __forceinline__ void chunk_mma(const __nv_bfloat16* sW,
        const __nv_bfloat16* sA, int lda, int kc, float (&acc)[8][4],
        int lrow, int lcol8, int mr0, int nc0)
{
#pragma unroll
    for (int k0 = 0; k0 < NK; k0 += 16) {
        unsigned a[4];
        ldsm4(a, (unsigned)__cvta_generic_to_shared(
                     sA + (mr0 + lrow) * lda + kc + k0 + lcol8));
        unsigned b[16];
#pragma unroll
        for (int np = 0; np < 4; np++)
            ldsm4t(b + np * 4, (unsigned)__cvta_generic_to_shared(
                       sW + (k0 + lrow) * WS2 + nc0 + np * 16 + lcol8));
#pragma unroll
        for (int nt = 0; nt < 8; nt++)
            mma16(acc[nt], a, b[(nt >> 1) * 4 + (nt & 1) * 2],
                              b[(nt >> 1) * 4 + (nt & 1) * 2 + 1]);
    }
}

__device__ __forceinline__ int pipe_gemm(int ci, int nc, int nchTotal, int lastRows,
        const __nv_bfloat16* __restrict__ gw, __nv_bfloat16* sWb,
        const __nv_bfloat16* sA, int lda, float (&acc)[8][4],
        int tid, int lrow, int lcol8, int mr0, int nc0)
{
    for (int cc = 0; cc < nc; cc++) {
        int nxt = ci + 1;
        if (nxt < nchTotal)
            prefetch_chunk(sWb + (nxt & 1) * CHUNKW, gw + (size_t)nxt * 4096,
                           (nxt == nchTotal - 1) ? lastRows : 32, tid);
        else
            commit_empty();
        wait1();
        __syncthreads();
        chunk_mma<32>(sWb + (ci & 1) * CHUNKW, sA, lda, cc * 32, acc,
                      lrow, lcol8, mr0, nc0);
        ci++;
        __syncthreads();
    }
    return ci;
}

__device__ __forceinline__ void epi_silu(const float (&acc)[8][4], const float* sb,
                                         __nv_bfloat16* s_A, int r, int c,
                                         int mr0, int nc0)
{
#pragma unroll
    for (int nt = 0; nt < 8; nt++) {
        int col = nc0 + nt * 8 + 2 * c;
        float b0 = sb[col], b1 = sb[col + 1];
        *(__nv_bfloat162*)(s_A + (mr0 + r) * SA + col) =
            __floats2bfloat162_rn(siluf(acc[nt][0] + b0), siluf(acc[nt][1] + b1));
        *(__nv_bfloat162*)(s_A + (mr0 + r + 8) * SA + col) =
            __floats2bfloat162_rn(siluf(acc[nt][2] + b0), siluf(acc[nt][3] + b1));
    }
}

__global__ void k_prep(const float* __restrict__ W_node, const float* __restrict__ fc1,
                       const float* __restrict__ fc2, const float* __restrict__ fc3,
                       const float* __restrict__ W_sh, const float* __restrict__ aW1,
                       const float* __restrict__ aW2)
{
    int i = blockIdx.x * blockDim.x + threadIdx.x;
    if (i < 432 * 128) {
        int row = i >> 7, col = i & 127;
        float v;
        if (row < 128)      v = W_node[row * 128 + col];
        else if (row < 160) v = fc1[(row - 128) * 128 + col];
        else if (row < 288) v = fc2[(row - 160) * 128 + col];
        else if (row < 416) v = fc3[(row - 288) * 128 + col];
        else                v = W_sh[(row - 416) * 128 + col];
        g_wmsg[i] = __float2bfloat16(v);
    }
    if (i < 288 * 128) {
        int row = i >> 7, col = i & 127;
        float v = (row < 160) ? aW1[row * 128 + col] : aW2[(row - 160) * 128 + col];
        g_watt[i] = __float2bfloat16(v);
    }
}

__global__ void k_init()
{
    int i = blockIdx.x * blockDim.x + threadIdx.x;
    int stride = gridDim.x * blockDim.x;
    for (int j = i; j < NN * DD; j += stride) g_agg[j] = 0.f;
    if (i < NH) { g_maxbits[i] = 0u; g_sum[i] = 0.f; }
}

__global__ void __launch_bounds__(256, 3)
k_att(const float* __restrict__ nf, const float* __restrict__ edge_attr,
      const float* __restrict__ ab1, const float* __restrict__ ab2,
      const float* __restrict__ aW3, const float* __restrict__ ab3,
      const int* __restrict__ edge_index)
{
    extern __shared__ char smem[];
    __nv_bfloat16* s_A  = (__nv_bfloat16*)smem;                // 21504
    __nv_bfloat16* s_Wb = (__nv_bfloat16*)(smem + 21504);      // 17408
    float*    s_aW3  = (float*)(smem + 38912);                 // 4096
    float*    s_bias = (float*)(smem + 43008);                 // 1024
    int*      s_src  = (int*)(smem + 44032);                   // 256
    int*      s_dst  = (int*)(smem + 44288);                   // 256
    unsigned* s_maxb = (unsigned*)(smem + 44544);              // 32

    const int tid = threadIdx.x, lane = tid & 31, wid = tid >> 5;
    const int r = lane >> 2, c = lane & 3;
    const int lrow = lane & 15, lcol8 = (lane >> 1) & 8;
    const int mr0 = (wid & 3) * 16, nc0 = (wid >> 2) * 64;
    const int e0 = blockIdx.x * TE;

    prefetch_chunk(s_Wb, g_watt, 32, tid);

    if (tid < TE) {
        s_src[tid] = edge_index[e0 + tid];
        s_dst[tid] = edge_index[EE + e0 + tid];
    }
    if (tid < NH) s_maxb[tid] = 0u;
    if (tid < 128) {
        s_bias[tid]       = ab1[tid];
        s_bias[128 + tid] = ab2[tid];
    }
    *(float4*)(s_aW3 + tid * 4) = *(const float4*)(aW3 + tid * 4);

    for (int idx = tid; idx < TE * 8; idx += 256) {
        int rr = idx >> 3, cc = (idx & 7) << 2;
        const float4 v = *(const float4*)(edge_attr + (size_t)(e0 + rr) * 32 + cc);
        *(__nv_bfloat162*)(s_A + rr * SA + 128 + cc)     = __floats2bfloat162_rn(v.x, v.y);
        *(__nv_bfloat162*)(s_A + rr * SA + 128 + cc + 2) = __floats2bfloat162_rn(v.z, v.w);
    }
    __syncthreads();
#pragma unroll
    for (int i = 0; i < 8; i++) {
        int rr = wid * 8 + i;
        const float2 vs = *(const float2*)(nf + (size_t)s_src[rr] * DD + lane * 2);
        const float2 vd = *(const float2*)(nf + (size_t)s_dst[rr] * DD + lane * 2);
        *(__nv_bfloat162*)(s_A + rr * SA + lane * 2)      = __floats2bfloat162_rn(vs.x, vs.y);
        *(__nv_bfloat162*)(s_A + rr * SA + 64 + lane * 2) = __floats2bfloat162_rn(vd.x, vd.y);
    }

    float acc[8][4];
    clr(acc);
    int ci = pipe_gemm(0, 5, 9, 32, g_watt, s_Wb, s_A, SA, acc, tid, lrow, lcol8, mr0, nc0);
    epi_silu(acc, s_bias, s_A, r, c, mr0, nc0);

    clr(acc);
    ci = pipe_gemm(ci, 4, 9, 32, g_watt, s_Wb, s_A, SA, acc, tid, lrow, lcol8, mr0, nc0);
    epi_silu(acc, s_bias + 128, s_A, r, c, mr0, nc0);
    __syncthreads();

    if (tid < TE) {
        float av[NH];
#pragma unroll
        for (int h = 0; h < NH; h++) av[h] = ab3[h];
        for (int k = 0; k < 128; k++) {
            float x = __bfloat162float(s_A[tid * SA + k]);
#pragma unroll
            for (int h = 0; h < NH; h++) av[h] += x * s_aW3[k * 8 + h];
        }
        float4* gp = (float4*)(g_a + (size_t)(e0 + tid) * NH);
        gp[0] = make_float4(av[0], av[1], av[2], av[3]);
        gp[1] = make_float4(av[4], av[5], av[6], av[7]);
#pragma unroll
        for (int h = 0; h < NH; h++) atomicMax(&s_maxb[h], encf(av[h]));
    }
    __syncthreads();
    if (tid < NH) atomicMax(&g_maxbits[tid], s_maxb[tid]);
}

__global__ void k_sumexp()
{
    __shared__ float s_sum[NH];
    if (threadIdx.x < NH) s_sum[threadIdx.x] = 0.f;
    __syncthreads();
    float mx[NH];
#pragma unroll
    for (int h = 0; h < NH; h++) mx[h] = decf(g_maxbits[h]);
    float loc[NH];
#pragma unroll
    for (int h = 0; h < NH; h++) loc[h] = 0.f;
    for (int e = blockIdx.x * blockDim.x + threadIdx.x; e < EE; e += gridDim.x * blockDim.x) {
        const float4 a0 = *(const float4*)(g_a + (size_t)e * NH);
        const float4 a1 = *(const float4*)(g_a + (size_t)e * NH + 4);
        loc[0] += __expf(a0.x - mx[0]); loc[1] += __expf(a0.y - mx[1]);
        loc[2] += __expf(a0.z - mx[2]); loc[3] += __expf(a0.w - mx[3]);
        loc[4] += __expf(a1.x - mx[4]); loc[5] += __expf(a1.y - mx[5]);
        loc[6] += __expf(a1.z - mx[6]); loc[7] += __expf(a1.w - mx[7]);
    }
#pragma unroll
    for (int h = 0; h < NH; h++) atomicAdd(&s_sum[h], loc[h]);
    __syncthreads();
    if (threadIdx.x < NH) atomicAdd(&g_sum[threadIdx.x], s_sum[threadIdx.x]);
}

__global__ void __launch_bounds__(256, 3)
k_msg(const float* __restrict__ nf, const float* __restrict__ edge_attr,
      const float* __restrict__ edge_sh,
      const float* __restrict__ b1, const float* __restrict__ b2,
      const float* __restrict__ b3, const int* __restrict__ edge_index)
{
    extern __shared__ char smem[];
    __nv_bfloat16* s_A  = (__nv_bfloat16*)smem;                 // 21504
    __nv_bfloat16* s_Wb = (__nv_bfloat16*)(smem + 21504);       // 17408
    __nv_bfloat16* s_xw = (__nv_bfloat16*)(smem + 38912);       // 17408
    __nv_bfloat16* s_sh = (__nv_bfloat16*)(smem + 56320);       // 3072
    __nv_bfloat16* s_ea = (__nv_bfloat16*)(smem + 59392);       // 5120
    float* s_bias = (float*)(smem + 64512);                     // 1536
    float* s_wt   = (float*)(smem + 66048);                     // 256
    int*   s_src  = (int*)(smem + 66304);                       // 256
    int*   s_dst  = (int*)(smem + 66560);                       // 256

    const int tid = threadIdx.x, lane = tid & 31, wid = tid >> 5;
    const int r = lane >> 2, c = lane & 3;
    const int lrow = lane & 15, lcol8 = (lane >> 1) & 8;
    const int mr0 = (wid & 3) * 16, nc0 = (wid >> 2) * 64;
    const int e0 = blockIdx.x * TE;

    prefetch_chunk(s_Wb, g_wmsg, 32, tid);

    if (tid < TE) {
        s_src[tid] = edge_index[e0 + tid];
        s_dst[tid] = edge_index[EE + e0 + tid];
    }
    if (tid < 128) {
        s_bias[tid]       = b1[tid];
        s_bias[128 + tid] = b2[tid];
        s_bias[256 + tid] = b3[tid];
    }
    if (tid < TE) {
        int e = e0 + tid;
        float w = 0.f;
#pragma unroll
        for (int h = 0; h < NH; h++)
            w += __expf(g_a[(size_t)e * NH + h] - decf(g_maxbits[h])) / g_sum[h];
        s_wt[tid] = w * 0.125f;
    }
    for (int idx = tid; idx < TE * 4; idx += 256) {
        int rr = idx >> 2, cc = (idx & 3) << 2;
        const float4 v = *(const float4*)(edge_sh + (size_t)(e0 + rr) * 16 + cc);
        *(__nv_bfloat162*)(s_sh + rr * SSH + cc)     = __floats2bfloat162_rn(v.x, v.y);
        *(__nv_bfloat162*)(s_sh + rr * SSH + cc + 2) = __floats2bfloat162_rn(v.z, v.w);
    }
    for (int idx = tid; idx < TE * 8; idx += 256) {
        int rr = idx >> 3, cc = (idx & 7) << 2;
        const float4 v = *(const float4*)(edge_attr + (size_t)(e0 + rr) * 32 + cc);
        *(__nv_bfloat162*)(s_ea + rr * SEA + cc)     = __floats2bfloat162_rn(v.x, v.y);
        *(__nv_bfloat162*)(s_ea + rr * SEA + cc + 2) = __floats2bfloat162_rn(v.z, v.w);
    }
    __syncthreads();
#pragma unroll
    for (int i = 0; i < 8; i++) {
        int rr = wid * 8 + i;
        const float4 v = *(const float4*)(nf + (size_t)s_src[rr] * DD + lane * 4);
        *(__nv_bfloat162*)(s_A + rr * SA + lane * 4)     = __floats2bfloat162_rn(v.x, v.y);
        *(__nv_bfloat162*)(s_A + rr * SA + lane * 4 + 2) = __floats2bfloat162_rn(v.z, v.w);
    }

    float acc[8][4];
    clr(acc);
    int ci = pipe_gemm(0, 4, 14, 16, g_wmsg, s_Wb, s_A, SA, acc, tid, lrow, lcol8, mr0, nc0);
#pragma unroll
    for (int nt = 0; nt < 8; nt++) {
        int col = nc0 + nt * 8 + 2 * c;
        *(__nv_bfloat162*)(s_xw + (mr0 + r) * XS + col) =
            __floats2bfloat162_rn(acc[nt][0], acc[nt][1]);
        *(__nv_bfloat162*)(s_xw + (mr0 + r + 8) * XS + col) =
            __floats2bfloat162_rn(acc[nt][2], acc[nt][3]);
    }

    clr(acc);
    ci = pipe_gemm(ci, 1, 14, 16, g_wmsg, s_Wb, s_ea, SEA, acc, tid, lrow, lcol8, mr0, nc0);
    epi_silu(acc, s_bias, s_A, r, c, mr0, nc0);

    clr(acc);
    ci = pipe_gemm(ci, 4, 14, 16, g_wmsg, s_Wb, s_A, SA, acc, tid, lrow, lcol8, mr0, nc0);
    epi_silu(acc, s_bias + 128, s_A, r, c, mr0, nc0);

    clr(acc);
    ci = pipe_gemm(ci, 4, 14, 16, g_wmsg, s_Wb, s_A, SA, acc, tid, lrow, lcol8, mr0, nc0);
#pragma unroll
    for (int nt = 0; nt < 8; nt++) {
        int col = nc0 + nt * 8 + 2 * c;
        float b0 = s_bias[256 + col], b1v = s_bias[256 + col + 1];
        *(__nv_bfloat162*)(s_A + (mr0 + r) * SA + col) =
            __floats2bfloat162_rn(acc[nt][0] + b0, acc[nt][1] + b1v);
        *(__nv_bfloat162*)(s_A + (mr0 + r + 8) * SA + col) =
            __floats2bfloat162_rn(acc[nt][2] + b0, acc[nt][3] + b1v);
    }

    clr(acc);
    commit_empty();
    wait1();
    __syncthreads();
    chunk_mma<16>(s_Wb + (ci & 1) * CHUNKW, s_sh, SSH, 0, acc, lrow, lcol8, mr0, nc0);

#pragma unroll
    for (int nt = 0; nt < 8; nt++) {
        int col = nc0 + nt * 8 + 2 * c;
        float w0 = s_wt[mr0 + r], w1 = s_wt[mr0 + r + 8];
        float2 sc0 = __bfloat1622float2(*(__nv_bfloat162*)(s_A + (mr0 + r) * SA + col));
        float2 sc1 = __bfloat1622float2(*(__nv_bfloat162*)(s_A + (mr0 + r + 8) * SA + col));
        float2 xw0 = __bfloat1622float2(*(__nv_bfloat162*)(s_xw + (mr0 + r) * XS + col));
        float2 xw1 = __bfloat1622float2(*(__nv_bfloat162*)(s_xw + (mr0 + r + 8) * XS + col));
        *(__nv_bfloat162*)(s_xw + (mr0 + r) * XS + col) = __floats2bfloat162_rn(
            siluf(xw0.x * sc0.x + acc[nt][0]) * w0, siluf(xw0.y * sc0.y + acc[nt][1]) * w0);
        *(__nv_bfloat162*)(s_xw + (mr0 + r + 8) * XS + col) = __floats2bfloat162_rn(
            siluf(xw1.x * sc1.x + acc[nt][2]) * w1, siluf(xw1.y * sc1.y + acc[nt][3]) * w1);
    }
    __syncthreads();

#pragma unroll
    for (int i = 0; i < 8; i++) {
        int rr = wid * 8 + i;
        int d = s_dst[rr];
        __nv_bfloat162 p0 = *(__nv_bfloat162*)(s_xw + rr * XS + lane * 4);
        __nv_bfloat162 p1 = *(__nv_bfloat162*)(s_xw + rr * XS + lane * 4 + 2);
        float2 f0 = __bfloat1622float2(p0), f1 = __bfloat1622float2(p1);
        float* p = g_agg + (size_t)d * DD + lane * 4;
        atomicAdd(p + 0, f0.x);
        atomicAdd(p + 1, f0.y);
        atomicAdd(p + 2, f1.x);
        atomicAdd(p + 3, f1.y);
    }
}

__global__ void k_node(const float* __restrict__ nf, const float* __restrict__ W_out,
                       float* __restrict__ out)
{
    extern __shared__ float smemf[];
    float* sW    = smemf;
    float* s_row = sW + 128 * 128;
    const int tid = threadIdx.x, tx = tid & 31, w = tid >> 5;
    for (int idx = tid; idx < 128 * 32; idx += 256) {
        int rr = idx >> 5, cc = (idx & 31) << 2;
        *(float4*)(sW + rr * 128 + cc) = *(const float4*)(W_out + (size_t)rr * 128 + cc);
    }
    __syncthreads();
    for (int n = blockIdx.x * 8 + w; n < NN; n += gridDim.x * 8) {
        float4 av = *(const float4*)(g_agg + (size_t)n * DD + tx * 4);
        __syncwarp();
        *(float4*)(s_row + w * 128 + tx * 4) = av;
        __syncwarp();
        float a0 = 0.f, a1 = 0.f, a2 = 0.f, a3 = 0.f;
#pragma unroll 8
        for (int k = 0; k < 128; k++) {
            float a = s_row[w * 128 + k];
            const float4 wv = *(const float4*)(sW + k * 128 + tx * 4);
            a0 += a * wv.x; a1 += a * wv.y; a2 += a * wv.z; a3 += a * wv.w;
        }
        const float4 x = *(const float4*)(nf + (size_t)n * DD + tx * 4);
        float v0 = x.x + a0, v1 = x.y + a1, v2 = x.z + a2, v3 = x.w + a3;
        float s = v0 + v1 + v2 + v3;
#pragma unroll
        for (int o = 16; o > 0; o >>= 1) s += __shfl_xor_sync(0xffffffffu, s, o);
        float mu = s * (1.f / 128.f);
        float d0 = v0 - mu, d1 = v1 - mu, d2 = v2 - mu, d3 = v3 - mu;
        float q = d0 * d0 + d1 * d1 + d2 * d2 + d3 * d3;
#pragma unroll
        for (int o = 16; o > 0; o >>= 1) q += __shfl_xor_sync(0xffffffffu, q, o);
        float rs = rsqrtf(q * (1.f / 128.f) + 1e-5f);
        float4 o4 = make_float4(d0 * rs, d1 * rs, d2 * rs, d3 * rs);
        *(float4*)(out + (size_t)n * DD + tx * 4) = o4;
    }
}

extern "C" void kernel_launch(void* const* d_in, const int* in_sizes, int n_in,
                              void* d_out, int out_size)
{
    const float* nf        = (const float*)d_in[0];
    const float* edge_attr = (const float*)d_in[1];
    const float* edge_sh   = (const float*)d_in[2];
    const float* W_node    = (const float*)d_in[3];
    const float* fc1 = (const float*)d_in[4];
    const float* b1  = (const float*)d_in[5];
    const float* fc2 = (const float*)d_in[6];
    const float* b2  = (const float*)d_in[7];
    const float* fc3 = (const float*)d_in[8];
    const float* b3  = (const float*)d_in[9];
    const float* W_sh = (const float*)d_in[10];
    const float* aW1 = (const float*)d_in[11];
    const float* ab1 = (const float*)d_in[12];
    const float* aW2 = (const float*)d_in[13];
    const float* ab2 = (const float*)d_in[14];
    const float* aW3 = (const float*)d_in[15];
    const float* ab3 = (const float*)d_in[16];
    const float* W_out = (const float*)d_in[17];
    const int* edge_index = (const int*)d_in[18];
    float* out = (float*)d_out;

    const int SMEM_ATT  = 44576;
    const int SMEM_MSG  = 66816;
    const int SMEM_NODE = (128 * 128 + 8 * 128) * 4;
    cudaFuncSetAttribute(k_att,  cudaFuncAttributeMaxDynamicSharedMemorySize, SMEM_ATT);
    cudaFuncSetAttribute(k_msg,  cudaFuncAttributeMaxDynamicSharedMemorySize, SMEM_MSG);
    cudaFuncSetAttribute(k_node, cudaFuncAttributeMaxDynamicSharedMemorySize, SMEM_NODE);

    k_prep<<<216, 256>>>(W_node, fc1, fc2, fc3, W_sh, aW1, aW2);
    k_init<<<2048, 256>>>();
    k_att<<<EE / TE, 256, SMEM_ATT>>>(nf, edge_attr, ab1, ab2, aW3, ab3, edge_index);
    k_sumexp<<<1024, 256>>>();
    k_msg<<<EE / TE, 256, SMEM_MSG>>>(nf, edge_attr, edge_sh, b1, b2, b3, edge_index);
    k_node<<<296, 256, SMEM_NODE>>>(nf, W_out, out);
}

// round 8
// speedup vs baseline: 2.1908x; 1.0471x over previous
#include <cuda_runtime.h>
#include <cuda_bf16.h>

#define NN 50000
#define EE 800000
#define DD 128
#define NH 8
#define TE 64
#define SA 168
#define WS2 136
#define SSH 24
#define SEA 40
#define XS 136
#define PS 136
#define CHUNKW (32 * WS2)

__device__ float    g_a[(size_t)EE * NH];
__device__ float    g_agg[(size_t)NN * DD];
__device__ unsigned g_maxbits[NH];
__device__ float    g_sum[NH];
__device__ __align__(256) __nv_bfloat16 g_wnp[256 * 128];   // aW1[0:128) | W_node
__device__ __align__(256) __nv_bfloat16 g_watt[160 * 128];  // aW1[128:160) | aW2
__device__ __align__(256) __nv_bfloat16 g_wmsg[304 * 128];  // fc1|fc2|fc3|W_sh
__device__ __align__(256) __nv_bfloat16 g_P1[(size_t)NN * DD];
__device__ __align__(256) __nv_bfloat16 g_P2[(size_t)NN * DD];
__device__ __align__(256) __nv_bfloat16 g_XW[(size_t)NN * DD];

__device__ __forceinline__ float siluf(float x) { return x / (1.f + __expf(-x)); }
__device__ __forceinline__ unsigned encf(float x) {
    unsigned u = __float_as_uint(x);
    return (u & 0x80000000u) ? ~u : (u | 0x80000000u);
}
__device__ __forceinline__ float decf(unsigned u) {
    return __uint_as_float((u & 0x80000000u) ? (u ^ 0x80000000u) : ~u);
}
__device__ __forceinline__ void ldsm4(unsigned (&r)[4], unsigned addr) {
    asm volatile("ldmatrix.sync.aligned.m8n8.x4.shared.b16 {%0,%1,%2,%3}, [%4];"
                 : "=r"(r[0]), "=r"(r[1]), "=r"(r[2]), "=r"(r[3]) : "r"(addr));
}
__device__ __forceinline__ void ldsm4t(unsigned* r, unsigned addr) {
    asm volatile("ldmatrix.sync.aligned.m8n8.x4.trans.shared.b16 {%0,%1,%2,%3}, [%4];"
                 : "=r"(r[0]), "=r"(r[1]), "=r"(r[2]), "=r"(r[3]) : "r"(addr));
}
__device__ __forceinline__ void mma16(float (&d)[4], const unsigned (&a)[4],
                                      unsigned b0, unsigned b1) {
    asm volatile(
        "mma.sync.aligned.m16n8k16.row.col.f32.bf16.bf16.f32 "
        "{%0,%1,%2,%3}, {%4,%5,%6,%7}, {%8,%9}, {%0,%1,%2,%3};\n"
        : "+f"(d[0]), "+f"(d[1]), "+f"(d[2]), "+f"(d[3])
        : "r"(a[0]), "r"(a[1]), "r"(a[2]), "r"(a[3]), "r"(b0), "r"(b1));
}
__device__ __forceinline__ void clr(float (&acc)[8][4]) {
#pragma unroll
    for (int i = 0; i < 8; i++)
#pragma unroll
        for (int j = 0; j < 4; j++) acc[i][j] = 0.f;
}

__device__ __forceinline__ void prefetch_chunk(__nv_bfloat16* sbuf,
        const __nv_bfloat16* __restrict__ gsrc, int nrows, int tid)
{
    for (int idx = tid; idx < nrows * 16; idx += 256) {
        int row = idx >> 4, seg = idx & 15;
        unsigned d = (unsigned)__cvta_generic_to_shared(sbuf + row * WS2) + seg * 16;
        const char* s = (const char*)(gsrc + (size_t)row * 128) + seg * 16;
        asm volatile("cp.async.cg.shared.global [%0], [%1], 16;" :: "r"(d), "l"(s));
    }
    asm volatile("cp.async.commit_group;" ::: "memory");
}
__device__ __forceinline__ void commit_empty() {
    asm volatile("cp.async.commit_group;" ::: "memory");
}
__device__ __forceinline__ void wait1() {
    asm volatile("cp.async.wait_group 1;" ::: "memory");
}

template<int NK>
__device__ __forceinline__ void chunk_mma(const __nv_bfloat16* sW,
        const __nv_bfloat16* sA, int lda, int kc, float (&acc)[8][4],
        int lrow, int lcol8, int mr0, int nc0)
{
#pragma unroll
    for (int k0 = 0; k0 < NK; k0 += 16) {
        unsigned a[4];
        ldsm4(a, (unsigned)__cvta_generic_to_shared(
                     sA + (mr0 + lrow) * lda + kc + k0 + lcol8));
        unsigned b[16];
#pragma unroll
        for (int np = 0; np < 4; np++)
            ldsm4t(b + np * 4, (unsigned)__cvta_generic_to_shared(
                       sW + (k0 + lrow) * WS2 + nc0 + np * 16 + lcol8));
#pragma unroll
        for (int nt = 0; nt < 8; nt++)
            mma16(acc[nt], a, b[(nt >> 1) * 4 + (nt & 1) * 2],
                              b[(nt >> 1) * 4 + (nt & 1) * 2 + 1]);
    }
}

__device__ __forceinline__ int pipe_gemm(int ci, int nc, int nchTotal, int lastRows,
        const __nv_bfloat16* __restrict__ gw, __nv_bfloat16* sWb,
        const __nv_bfloat16* sA, int lda, float (&acc)[8][4],
        int tid, int lrow, int lcol8, int mr0, int nc0)
{
    for (int cc = 0; cc < nc; cc++) {
        int nxt = ci + 1;
        if (nxt < nchTotal)
            prefetch_chunk(sWb + (nxt & 1) * CHUNKW, gw + (size_t)nxt * 4096,
                           (nxt == nchTotal - 1) ? lastRows : 32, tid);
        else
            commit_empty();
        wait1();
        __syncthreads();
        chunk_mma<32>(sWb + (ci & 1) * CHUNKW, sA, lda, cc * 32, acc,
                      lrow, lcol8, mr0, nc0);
        ci++;
        __syncthreads();
    }
    return ci;
}

__device__ __forceinline__ void epi_silu(const float (&acc)[8][4], const float* sb,
                                         __nv_bfloat16* s_A, int r, int c,
                                         int mr0, int nc0)
{
#pragma unroll
    for (int nt = 0; nt < 8; nt++) {
        int col = nc0 + nt * 8 + 2 * c;
        float b0 = sb[col], b1 = sb[col + 1];
        *(__nv_bfloat162*)(s_A + (mr0 + r) * SA + col) =
            __floats2bfloat162_rn(siluf(acc[nt][0] + b0), siluf(acc[nt][1] + b1));
        *(__nv_bfloat162*)(s_A + (mr0 + r + 8) * SA + col) =
            __floats2bfloat162_rn(siluf(acc[nt][2] + b0), siluf(acc[nt][3] + b1));
    }
}

// ---------------- weight packing ----------------
__global__ void k_prep(const float* __restrict__ W_node, const float* __restrict__ fc1,
                       const float* __restrict__ fc2, const float* __restrict__ fc3,
                       const float* __restrict__ W_sh, const float* __restrict__ aW1,
                       const float* __restrict__ aW2)
{
    int i = blockIdx.x * blockDim.x + threadIdx.x;
    int row = i >> 7, col = i & 127;
    if (i < 256 * 128) {
        float v = (row < 128) ? aW1[row * 128 + col] : W_node[(row - 128) * 128 + col];
        g_wnp[i] = __float2bfloat16(v);
    }
    if (i < 160 * 128) {
        float v = (row < 32) ? aW1[(128 + row) * 128 + col] : aW2[(row - 32) * 128 + col];
        g_watt[i] = __float2bfloat16(v);
    }
    if (i < 304 * 128) {
        float v;
        if (row < 32)       v = fc1[row * 128 + col];
        else if (row < 160) v = fc2[(row - 32) * 128 + col];
        else if (row < 288) v = fc3[(row - 160) * 128 + col];
        else                v = W_sh[(row - 288) * 128 + col];
        g_wmsg[i] = __float2bfloat16(v);
    }
}

__global__ void k_init()
{
    int i = blockIdx.x * blockDim.x + threadIdx.x;
    int stride = gridDim.x * blockDim.x;
    for (int j = i; j < NN * DD; j += stride) g_agg[j] = 0.f;
    if (i < NH) { g_maxbits[i] = 0u; g_sum[i] = 0.f; }
}

// ---------------- node projections: P1, P2, XW ----------------
__global__ void __launch_bounds__(256, 3)
k_nodeproj(const float* __restrict__ nf)
{
    extern __shared__ char smem[];
    __nv_bfloat16* s_A  = (__nv_bfloat16*)smem;             // 21504
    __nv_bfloat16* s_Wb = (__nv_bfloat16*)(smem + 21504);   // 17408

    const int tid = threadIdx.x, lane = tid & 31, wid = tid >> 5;
    const int r = lane >> 2, c = lane & 3;
    const int lrow = lane & 15, lcol8 = (lane >> 1) & 8;
    const int mr0 = (wid & 3) * 16, nc0 = (wid >> 2) * 64;
    const int n0 = blockIdx.x * 64;

    prefetch_chunk(s_Wb, g_wnp, 32, tid);

#pragma unroll
    for (int i = 0; i < 8; i++) {
        int rr = wid * 8 + i;
        int n = n0 + rr; if (n >= NN) n = NN - 1;
        const float4 v = *(const float4*)(nf + (size_t)n * DD + lane * 4);
        *(__nv_bfloat162*)(s_A + rr * SA + lane * 4)     = __floats2bfloat162_rn(v.x, v.y);
        *(__nv_bfloat162*)(s_A + rr * SA + lane * 4 + 2) = __floats2bfloat162_rn(v.z, v.w);
    }

    float acc[8][4];
    // P1 = nf[:,0:64] @ aW1[0:64)  (chunks 0-1)
    clr(acc);
    int ci = pipe_gemm(0, 2, 8, 32, g_wnp, s_Wb, s_A, SA, acc, tid, lrow, lcol8, mr0, nc0);
#pragma unroll
    for (int nt = 0; nt < 8; nt++) {
        int col = nc0 + nt * 8 + 2 * c;
        int row0 = n0 + mr0 + r, row1 = row0 + 8;
        if (row0 < NN) *(__nv_bfloat162*)(g_P1 + (size_t)row0 * DD + col) =
            __floats2bfloat162_rn(acc[nt][0], acc[nt][1]);
        if (row1 < NN) *(__nv_bfloat162*)(g_P1 + (size_t)row1 * DD + col) =
            __floats2bfloat162_rn(acc[nt][2], acc[nt][3]);
    }
    // P2 = nf[:,0:64] @ aW1[64:128)  (chunks 2-3)
    clr(acc);
    ci = pipe_gemm(ci, 2, 8, 32, g_wnp, s_Wb, s_A, SA, acc, tid, lrow, lcol8, mr0, nc0);
#pragma unroll
    for (int nt = 0; nt < 8; nt++) {
        int col = nc0 + nt * 8 + 2 * c;
        int row0 = n0 + mr0 + r, row1 = row0 + 8;
        if (row0 < NN) *(__nv_bfloat162*)(g_P2 + (size_t)row0 * DD + col) =
            __floats2bfloat162_rn(acc[nt][0], acc[nt][1]);
        if (row1 < NN) *(__nv_bfloat162*)(g_P2 + (size_t)row1 * DD + col) =
            __floats2bfloat162_rn(acc[nt][2], acc[nt][3]);
    }
    // XW = nf @ W_node  (chunks 4-7)
    clr(acc);
    ci = pipe_gemm(ci, 4, 8, 32, g_wnp, s_Wb, s_A, SA, acc, tid, lrow, lcol8, mr0, nc0);
#pragma unroll
    for (int nt = 0; nt < 8; nt++) {
        int col = nc0 + nt * 8 + 2 * c;
        int row0 = n0 + mr0 + r, row1 = row0 + 8;
        if (row0 < NN) *(__nv_bfloat162*)(g_XW + (size_t)row0 * DD + col) =
            __floats2bfloat162_rn(acc[nt][0], acc[nt][1]);
        if (row1 < NN) *(__nv_bfloat162*)(g_XW + (size_t)row1 * DD + col) =
            __floats2bfloat162_rn(acc[nt][2], acc[nt][3]);
    }
}

// ---------------- K1: attention logits ----------------
// smem: s_A 21504 | s_Wb 17408 | s_pd 17408 | s_ea 5120 | s_aW3 4096 |
//       bias 1024 | src 256 | dst 256 | maxb 32 => 67104
__global__ void __launch_bounds__(256, 3)
k_att(const float* __restrict__ edge_attr,
      const float* __restrict__ ab1, const float* __restrict__ ab2,
      const float* __restrict__ aW3, const float* __restrict__ ab3,
      const int* __restrict__ edge_index)
{
    extern __shared__ char smem[];
    __nv_bfloat16* s_A  = (__nv_bfloat16*)smem;                 // 21504
    __nv_bfloat16* s_Wb = (__nv_bfloat16*)(smem + 21504);       // 17408
    __nv_bfloat16* s_pd = (__nv_bfloat16*)(smem + 38912);       // 17408
    __nv_bfloat16* s_ea = (__nv_bfloat16*)(smem + 56320);       // 5120
    float*    s_aW3  = (float*)(smem + 61440);                  // 4096
    float*    s_bias = (float*)(smem + 65536);                  // 1024
    int*      s_src  = (int*)(smem + 66560);                    // 256
    int*      s_dst  = (int*)(smem + 66816);                    // 256
    unsigned* s_maxb = (unsigned*)(smem + 67072);               // 32

    const int tid = threadIdx.x, lane = tid & 31, wid = tid >> 5;
    const int r = lane >> 2, c = lane & 3;
    const int lrow = lane & 15, lcol8 = (lane >> 1) & 8;
    const int mr0 = (wid & 3) * 16, nc0 = (wid >> 2) * 64;
    const int e0 = blockIdx.x * TE;

    prefetch_chunk(s_Wb, g_watt, 32, tid);

    if (tid < TE) {
        s_src[tid] = edge_index[e0 + tid];
        s_dst[tid] = edge_index[EE + e0 + tid];
    }
    if (tid < NH) s_maxb[tid] = 0u;
    if (tid < 128) {
        s_bias[tid]       = ab1[tid];
        s_bias[128 + tid] = ab2[tid];
    }
    *(float4*)(s_aW3 + tid * 4) = *(const float4*)(aW3 + tid * 4);

    for (int idx = tid; idx < TE * 8; idx += 256) {
        int rr = idx >> 3, cc = (idx & 7) << 2;
        const float4 v = *(const float4*)(edge_attr + (size_t)(e0 + rr) * 32 + cc);
        *(__nv_bfloat162*)(s_ea + rr * SEA + cc)     = __floats2bfloat162_rn(v.x, v.y);
        *(__nv_bfloat162*)(s_ea + rr * SEA + cc + 2) = __floats2bfloat162_rn(v.z, v.w);
    }
    __syncthreads();
    // gather P1[src] + P2[dst] -> s_pd (warp-private rows)
#pragma unroll
    for (int i = 0; i < 8; i++) {
        int rr = wid * 8 + i;
        int s = s_src[rr], d = s_dst[rr];
        __nv_bfloat162 a0 = *(const __nv_bfloat162*)(g_P1 + (size_t)s * DD + lane * 4);
        __nv_bfloat162 a1 = *(const __nv_bfloat162*)(g_P1 + (size_t)s * DD + lane * 4 + 2);
        __nv_bfloat162 b0 = *(const __nv_bfloat162*)(g_P2 + (size_t)d * DD + lane * 4);
        __nv_bfloat162 b1 = *(const __nv_bfloat162*)(g_P2 + (size_t)d * DD + lane * 4 + 2);
        float2 f0 = __bfloat1622float2(a0), f1 = __bfloat1622float2(b0);
        float2 f2 = __bfloat1622float2(a1), f3 = __bfloat1622float2(b1);
        *(__nv_bfloat162*)(s_pd + rr * PS + lane * 4) =
            __floats2bfloat162_rn(f0.x + f1.x, f0.y + f1.y);
        *(__nv_bfloat162*)(s_pd + rr * PS + lane * 4 + 2) =
            __floats2bfloat162_rn(f2.x + f3.x, f2.y + f3.y);
    }

    float acc[8][4];
    // layer1: ea @ aW1_e (chunk 0), epilogue adds pd + ab1
    clr(acc);
    int ci = pipe_gemm(0, 1, 5, 32, g_watt, s_Wb, s_ea, SEA, acc, tid, lrow, lcol8, mr0, nc0);
#pragma unroll
    for (int nt = 0; nt < 8; nt++) {
        int col = nc0 + nt * 8 + 2 * c;
        float b0 = s_bias[col], b1 = s_bias[col + 1];
        float2 p0 = __bfloat1622float2(*(const __nv_bfloat162*)(s_pd + (mr0 + r) * PS + col));
        float2 p1 = __bfloat1622float2(*(const __nv_bfloat162*)(s_pd + (mr0 + r + 8) * PS + col));
        *(__nv_bfloat162*)(s_A + (mr0 + r) * SA + col) = __floats2bfloat162_rn(
            siluf(acc[nt][0] + p0.x + b0), siluf(acc[nt][1] + p0.y + b1));
        *(__nv_bfloat162*)(s_A + (mr0 + r + 8) * SA + col) = __floats2bfloat162_rn(
            siluf(acc[nt][2] + p1.x + b0), siluf(acc[nt][3] + p1.y + b1));
    }

    // layer2: aW2 (chunks 1-4)
    clr(acc);
    ci = pipe_gemm(ci, 4, 5, 32, g_watt, s_Wb, s_A, SA, acc, tid, lrow, lcol8, mr0, nc0);
    epi_silu(acc, s_bias + 128, s_A, r, c, mr0, nc0);
    __syncthreads();

    if (tid < TE) {
        float av[NH];
#pragma unroll
        for (int h = 0; h < NH; h++) av[h] = ab3[h];
        for (int k = 0; k < 128; k++) {
            float x = __bfloat162float(s_A[tid * SA + k]);
#pragma unroll
            for (int h = 0; h < NH; h++) av[h] += x * s_aW3[k * 8 + h];
        }
        float4* gp = (float4*)(g_a + (size_t)(e0 + tid) * NH);
        gp[0] = make_float4(av[0], av[1], av[2], av[3]);
        gp[1] = make_float4(av[4], av[5], av[6], av[7]);
#pragma unroll
        for (int h = 0; h < NH; h++) atomicMax(&s_maxb[h], encf(av[h]));
    }
    __syncthreads();
    if (tid < NH) atomicMax(&g_maxbits[tid], s_maxb[tid]);
}

__global__ void k_sumexp()
{
    __shared__ float s_sum[NH];
    if (threadIdx.x < NH) s_sum[threadIdx.x] = 0.f;
    __syncthreads();
    float mx[NH];
#pragma unroll
    for (int h = 0; h < NH; h++) mx[h] = decf(g_maxbits[h]);
    float loc[NH];
#pragma unroll
    for (int h = 0; h < NH; h++) loc[h] = 0.f;
    for (int e = blockIdx.x * blockDim.x + threadIdx.x; e < EE; e += gridDim.x * blockDim.x) {
        const float4 a0 = *(const float4*)(g_a + (size_t)e * NH);
        const float4 a1 = *(const float4*)(g_a + (size_t)e * NH + 4);
        loc[0] += __expf(a0.x - mx[0]); loc[1] += __expf(a0.y - mx[1]);
        loc[2] += __expf(a0.z - mx[2]); loc[3] += __expf(a0.w - mx[3]);
        loc[4] += __expf(a1.x - mx[4]); loc[5] += __expf(a1.y - mx[5]);
        loc[6] += __expf(a1.z - mx[6]); loc[7] += __expf(a1.w - mx[7]);
    }
#pragma unroll
    for (int h = 0; h < NH; h++) atomicAdd(&s_sum[h], loc[h]);
    __syncthreads();
    if (threadIdx.x < NH) atomicAdd(&g_sum[threadIdx.x], s_sum[threadIdx.x]);
}

// ---------------- K3: message MLP + weighted scatter ----------------
__global__ void __launch_bounds__(256, 3)
k_msg(const float* __restrict__ edge_attr, const float* __restrict__ edge_sh,
      const float* __restrict__ b1, const float* __restrict__ b2,
      const float* __restrict__ b3, const int* __restrict__ edge_index)
{
    extern __shared__ char smem[];
    __nv_bfloat16* s_A  = (__nv_bfloat16*)smem;                 // 21504
    __nv_bfloat16* s_Wb = (__nv_bfloat16*)(smem + 21504);       // 17408
    __nv_bfloat16* s_xw = (__nv_bfloat16*)(smem + 38912);       // 17408
    __nv_bfloat16* s_sh = (__nv_bfloat16*)(smem + 56320);       // 3072
    __nv_bfloat16* s_ea = (__nv_bfloat16*)(smem + 59392);       // 5120
    float* s_bias = (float*)(smem + 64512);                     // 1536
    float* s_wt   = (float*)(smem + 66048);                     // 256
    int*   s_src  = (int*)(smem + 66304);                       // 256
    int*   s_dst  = (int*)(smem + 66560);                       // 256

    const int tid = threadIdx.x, lane = tid & 31, wid = tid >> 5;
    const int r = lane >> 2, c = lane & 3;
    const int lrow = lane & 15, lcol8 = (lane >> 1) & 8;
    const int mr0 = (wid & 3) * 16, nc0 = (wid >> 2) * 64;
    const int e0 = blockIdx.x * TE;

    prefetch_chunk(s_Wb, g_wmsg, 32, tid);

    if (tid < TE) {
        s_src[tid] = edge_index[e0 + tid];
        s_dst[tid] = edge_index[EE + e0 + tid];
    }
    if (tid < 128) {
        s_bias[tid]       = b1[tid];
        s_bias[128 + tid] = b2[tid];
        s_bias[256 + tid] = b3[tid];
    }
    if (tid < TE) {
        int e = e0 + tid;
        float w = 0.f;
#pragma unroll
        for (int h = 0; h < NH; h++)
            w += __expf(g_a[(size_t)e * NH + h] - decf(g_maxbits[h])) / g_sum[h];
        s_wt[tid] = w * 0.125f;
    }
    for (int idx = tid; idx < TE * 4; idx += 256) {
        int rr = idx >> 2, cc = (idx & 3) << 2;
        const float4 v = *(const float4*)(edge_sh + (size_t)(e0 + rr) * 16 + cc);
        *(__nv_bfloat162*)(s_sh + rr * SSH + cc)     = __floats2bfloat162_rn(v.x, v.y);
        *(__nv_bfloat162*)(s_sh + rr * SSH + cc + 2) = __floats2bfloat162_rn(v.z, v.w);
    }
    for (int idx = tid; idx < TE * 8; idx += 256) {
        int rr = idx >> 3, cc = (idx & 7) << 2;
        const float4 v = *(const float4*)(edge_attr + (size_t)(e0 + rr) * 32 + cc);
        *(__nv_bfloat162*)(s_ea + rr * SEA + cc)     = __floats2bfloat162_rn(v.x, v.y);
        *(__nv_bfloat162*)(s_ea + rr * SEA + cc + 2) = __floats2bfloat162_rn(v.z, v.w);
    }
    __syncthreads();
    // gather XW[src] -> s_xw (warp-private rows, bf16 copy)
#pragma unroll
    for (int i = 0; i < 8; i++) {
        int rr = wid * 8 + i;
        int s = s_src[rr];
        const uint2 v = *(const uint2*)(g_XW + (size_t)s * DD + lane * 4);
        *(uint2*)(s_xw + rr * XS + lane * 4) = v;
    }

    float acc[8][4];
    // fc1 (chunk 0, A = s_ea)
    clr(acc);
    int ci = pipe_gemm(0, 1, 10, 16, g_wmsg, s_Wb, s_ea, SEA, acc, tid, lrow, lcol8, mr0, nc0);
    epi_silu(acc, s_bias, s_A, r, c, mr0, nc0);

    // fc2 (chunks 1-4)
    clr(acc);
    ci = pipe_gemm(ci, 4, 10, 16, g_wmsg, s_Wb, s_A, SA, acc, tid, lrow, lcol8, mr0, nc0);
    epi_silu(acc, s_bias + 128, s_A, r, c, mr0, nc0);

    // fc3 (chunks 5-8) -> scale = fc3 + b3 into s_A (frag-owned)
    clr(acc);
    ci = pipe_gemm(ci, 4, 10, 16, g_wmsg, s_Wb, s_A, SA, acc, tid, lrow, lcol8, mr0, nc0);
#pragma unroll
    for (int nt = 0; nt < 8; nt++) {
        int col = nc0 + nt * 8 + 2 * c;
        float b0 = s_bias[256 + col], b1v = s_bias[256 + col + 1];
        *(__nv_bfloat162*)(s_A + (mr0 + r) * SA + col) =
            __floats2bfloat162_rn(acc[nt][0] + b0, acc[nt][1] + b1v);
        *(__nv_bfloat162*)(s_A + (mr0 + r + 8) * SA + col) =
            __floats2bfloat162_rn(acc[nt][2] + b0, acc[nt][3] + b1v);
    }

    // W_sh (chunk 9, 16 rows, A = s_sh)
    clr(acc);
    commit_empty();
    wait1();
    __syncthreads();
    chunk_mma<16>(s_Wb + (ci & 1) * CHUNKW, s_sh, SSH, 0, acc, lrow, lcol8, mr0, nc0);

    // msg = silu(xw * scale + shp) * wt -> s_xw
#pragma unroll
    for (int nt = 0; nt < 8; nt++) {
        int col = nc0 + nt * 8 + 2 * c;
        float w0 = s_wt[mr0 + r], w1 = s_wt[mr0 + r + 8];
        float2 sc0 = __bfloat1622float2(*(__nv_bfloat162*)(s_A + (mr0 + r) * SA + col));
        float2 sc1 = __bfloat1622float2(*(__nv_bfloat162*)(s_A + (mr0 + r + 8) * SA + col));
        float2 xw0 = __bfloat1622float2(*(__nv_bfloat162*)(s_xw + (mr0 + r) * XS + col));
        float2 xw1 = __bfloat1622float2(*(__nv_bfloat162*)(s_xw + (mr0 + r + 8) * XS + col));
        *(__nv_bfloat162*)(s_xw + (mr0 + r) * XS + col) = __floats2bfloat162_rn(
            siluf(xw0.x * sc0.x + acc[nt][0]) * w0, siluf(xw0.y * sc0.y + acc[nt][1]) * w0);
        *(__nv_bfloat162*)(s_xw + (mr0 + r + 8) * XS + col) = __floats2bfloat162_rn(
            siluf(xw1.x * sc1.x + acc[nt][2]) * w1, siluf(xw1.y * sc1.y + acc[nt][3]) * w1);
    }
    __syncthreads();

#pragma unroll
    for (int i = 0; i < 8; i++) {
        int rr = wid * 8 + i;
        int d = s_dst[rr];
        __nv_bfloat162 p0 = *(__nv_bfloat162*)(s_xw + rr * XS + lane * 4);
        __nv_bfloat162 p1 = *(__nv_bfloat162*)(s_xw + rr * XS + lane * 4 + 2);
        float2 f0 = __bfloat1622float2(p0), f1 = __bfloat1622float2(p1);
        float* p = g_agg + (size_t)d * DD + lane * 4;
        atomicAdd(p + 0, f0.x);
        atomicAdd(p + 1, f0.y);
        atomicAdd(p + 2, f1.x);
        atomicAdd(p + 3, f1.y);
    }
}

__global__ void k_node(const float* __restrict__ nf, const float* __restrict__ W_out,
                       float* __restrict__ out)
{
    extern __shared__ float smemf[];
    float* sW    = smemf;
    float* s_row = sW + 128 * 128;
    const int tid = threadIdx.x, tx = tid & 31, w = tid >> 5;
    for (int idx = tid; idx < 128 * 32; idx += 256) {
        int rr = idx >> 5, cc = (idx & 31) << 2;
        *(float4*)(sW + rr * 128 + cc) = *(const float4*)(W_out + (size_t)rr * 128 + cc);
    }
    __syncthreads();
    for (int n = blockIdx.x * 8 + w; n < NN; n += gridDim.x * 8) {
        float4 av = *(const float4*)(g_agg + (size_t)n * DD + tx * 4);
        __syncwarp();
        *(float4*)(s_row + w * 128 + tx * 4) = av;
        __syncwarp();
        float a0 = 0.f, a1 = 0.f, a2 = 0.f, a3 = 0.f;
#pragma unroll 8
        for (int k = 0; k < 128; k++) {
            float a = s_row[w * 128 + k];
            const float4 wv = *(const float4*)(sW + k * 128 + tx * 4);
            a0 += a * wv.x; a1 += a * wv.y; a2 += a * wv.z; a3 += a * wv.w;
        }
        const float4 x = *(const float4*)(nf + (size_t)n * DD + tx * 4);
        float v0 = x.x + a0, v1 = x.y + a1, v2 = x.z + a2, v3 = x.w + a3;
        float s = v0 + v1 + v2 + v3;
#pragma unroll
        for (int o = 16; o > 0; o >>= 1) s += __shfl_xor_sync(0xffffffffu, s, o);
        float mu = s * (1.f / 128.f);
        float d0 = v0 - mu, d1 = v1 - mu, d2 = v2 - mu, d3 = v3 - mu;
        float q = d0 * d0 + d1 * d1 + d2 * d2 + d3 * d3;
#pragma unroll
        for (int o = 16; o > 0; o >>= 1) q += __shfl_xor_sync(0xffffffffu, q, o);
        float rs = rsqrtf(q * (1.f / 128.f) + 1e-5f);
        float4 o4 = make_float4(d0 * rs, d1 * rs, d2 * rs, d3 * rs);
        *(float4*)(out + (size_t)n * DD + tx * 4) = o4;
    }
}

extern "C" void kernel_launch(void* const* d_in, const int* in_sizes, int n_in,
                              void* d_out, int out_size)
{
    const float* nf        = (const float*)d_in[0];
    const float* edge_attr = (const float*)d_in[1];
    const float* edge_sh   = (const float*)d_in[2];
    const float* W_node    = (const float*)d_in[3];
    const float* fc1 = (const float*)d_in[4];
    const float* b1  = (const float*)d_in[5];
    const float* fc2 = (const float*)d_in[6];
    const float* b2  = (const float*)d_in[7];
    const float* fc3 = (const float*)d_in[8];
    const float* b3  = (const float*)d_in[9];
    const float* W_sh = (const float*)d_in[10];
    const float* aW1 = (const float*)d_in[11];
    const float* ab1 = (const float*)d_in[12];
    const float* aW2 = (const float*)d_in[13];
    const float* ab2 = (const float*)d_in[14];
    const float* aW3 = (const float*)d_in[15];
    const float* ab3 = (const float*)d_in[16];
    const float* W_out = (const float*)d_in[17];
    const int* edge_index = (const int*)d_in[18];
    float* out = (float*)d_out;

    const int SMEM_NP   = 38912;
    const int SMEM_ATT  = 67104;
    const int SMEM_MSG  = 66816;
    const int SMEM_NODE = (128 * 128 + 8 * 128) * 4;
    cudaFuncSetAttribute(k_nodeproj, cudaFuncAttributeMaxDynamicSharedMemorySize, SMEM_NP);
    cudaFuncSetAttribute(k_att,  cudaFuncAttributeMaxDynamicSharedMemorySize, SMEM_ATT);
    cudaFuncSetAttribute(k_msg,  cudaFuncAttributeMaxDynamicSharedMemorySize, SMEM_MSG);
    cudaFuncSetAttribute(k_node, cudaFuncAttributeMaxDynamicSharedMemorySize, SMEM_NODE);

    k_prep<<<128, 256>>>(W_node, fc1, fc2, fc3, W_sh, aW1, aW2);
    k_init<<<2048, 256>>>();
    k_nodeproj<<<(NN + 63) / 64, 256, SMEM_NP>>>(nf);
    k_att<<<EE / TE, 256, SMEM_ATT>>>(edge_attr, ab1, ab2, aW3, ab3, edge_index);
    k_sumexp<<<1024, 256>>>();
    k_msg<<<EE / TE, 256, SMEM_MSG>>>(edge_attr, edge_sh, b1, b2, b3, edge_index);
    k_node<<<296, 256, SMEM_NODE>>>(nf, W_out, out);
}

// round 9
// speedup vs baseline: 2.8931x; 1.3205x over previous
#include <cuda_runtime.h>
#include <cuda_bf16.h>

#define NN 50000
#define EE 800000
#define DD 128
#define NH 8
#define TE 64
#define SA 168
#define WS2 136
#define SSH 24
#define SEA 40
#define XS 136
#define PS 136
#define CHUNKW (32 * WS2)

__device__ float    g_a[(size_t)EE * NH];     // exp(logit) per edge/head
__device__ float    g_agg[(size_t)NN * DD];
__device__ float    g_sum[NH];
__device__ __align__(256) __nv_bfloat16 g_wnp[256 * 128];   // aW1[0:128) | W_node
__device__ __align__(256) __nv_bfloat16 g_watt[160 * 128];  // aW1[128:160) | aW2
__device__ __align__(256) __nv_bfloat16 g_wmsg[304 * 128];  // fc1|fc2|fc3|W_sh
__device__ __align__(256) __nv_bfloat16 g_w3[128 * 8];      // aW3 bf16
__device__ __align__(256) __nv_bfloat16 g_P1[(size_t)NN * DD];
__device__ __align__(256) __nv_bfloat16 g_P2[(size_t)NN * DD];
__device__ __align__(256) __nv_bfloat16 g_XW[(size_t)NN * DD];

__device__ __forceinline__ float siluf(float x) {
    float t;
    asm("tanh.approx.f32 %0, %1;" : "=f"(t) : "f"(x * 0.5f));
    return 0.5f * x * (1.f + t);
}
__device__ __forceinline__ void ldsm4(unsigned (&r)[4], unsigned addr) {
    asm volatile("ldmatrix.sync.aligned.m8n8.x4.shared.b16 {%0,%1,%2,%3}, [%4];"
                 : "=r"(r[0]), "=r"(r[1]), "=r"(r[2]), "=r"(r[3]) : "r"(addr));
}
__device__ __forceinline__ void ldsm4t(unsigned* r, unsigned addr) {
    asm volatile("ldmatrix.sync.aligned.m8n8.x4.trans.shared.b16 {%0,%1,%2,%3}, [%4];"
                 : "=r"(r[0]), "=r"(r[1]), "=r"(r[2]), "=r"(r[3]) : "r"(addr));
}
__device__ __forceinline__ void ldsm2t(unsigned& r0, unsigned& r1, unsigned addr) {
    asm volatile("ldmatrix.sync.aligned.m8n8.x2.trans.shared.b16 {%0,%1}, [%2];"
                 : "=r"(r0), "=r"(r1) : "r"(addr));
}
__device__ __forceinline__ void mma16(float (&d)[4], const unsigned (&a)[4],
                                      unsigned b0, unsigned b1) {
    asm volatile(
        "mma.sync.aligned.m16n8k16.row.col.f32.bf16.bf16.f32 "
        "{%0,%1,%2,%3}, {%4,%5,%6,%7}, {%8,%9}, {%0,%1,%2,%3};\n"
        : "+f"(d[0]), "+f"(d[1]), "+f"(d[2]), "+f"(d[3])
        : "r"(a[0]), "r"(a[1]), "r"(a[2]), "r"(a[3]), "r"(b0), "r"(b1));
}
__device__ __forceinline__ void clr(float (&acc)[8][4]) {
#pragma unroll
    for (int i = 0; i < 8; i++)
#pragma unroll
        for (int j = 0; j < 4; j++) acc[i][j] = 0.f;
}

__device__ __forceinline__ void prefetch_chunk(__nv_bfloat16* sbuf,
        const __nv_bfloat16* __restrict__ gsrc, int nrows, int tid)
{
    for (int idx = tid; idx < nrows * 16; idx += 256) {
        int row = idx >> 4, seg = idx & 15;
        unsigned d = (unsigned)__cvta_generic_to_shared(sbuf + row * WS2) + seg * 16;
        const char* s = (const char*)(gsrc + (size_t)row * 128) + seg * 16;
        asm volatile("cp.async.cg.shared.global [%0], [%1], 16;" :: "r"(d), "l"(s));
    }
    asm volatile("cp.async.commit_group;" ::: "memory");
}
__device__ __forceinline__ void commit_empty() {
    asm volatile("cp.async.commit_group;" ::: "memory");
}
__device__ __forceinline__ void wait1() {
    asm volatile("cp.async.wait_group 1;" ::: "memory");
}

template<int NK>
__device__ __forceinline__ void chunk_mma(const __nv_bfloat16* sW,
        const __nv_bfloat16* sA, int lda, int kc, float (&acc)[8][4],
        int lrow, int lcol8, int mr0, int nc0)
{
#pragma unroll
    for (int k0 = 0; k0 < NK; k0 += 16) {
        unsigned a[4];
        ldsm4(a, (unsigned)__cvta_generic_to_shared(
                     sA + (mr0 + lrow) * lda + kc + k0 + lcol8));
        unsigned b[16];
#pragma unroll
        for (int np = 0; np < 4; np++)
            ldsm4t(b + np * 4, (unsigned)__cvta_generic_to_shared(
                       sW + (k0 + lrow) * WS2 + nc0 + np * 16 + lcol8));
#pragma unroll
        for (int nt = 0; nt < 8; nt++)
            mma16(acc[nt], a, b[(nt >> 1) * 4 + (nt & 1) * 2],
                              b[(nt >> 1) * 4 + (nt & 1) * 2 + 1]);
    }
}

__device__ __forceinline__ int pipe_gemm(int ci, int nc, int nchTotal, int lastRows,
        const __nv_bfloat16* __restrict__ gw, __nv_bfloat16* sWb,
        const __nv_bfloat16* sA, int lda, float (&acc)[8][4],
        int tid, int lrow, int lcol8, int mr0, int nc0)
{
    for (int cc = 0; cc < nc; cc++) {
        int nxt = ci + 1;
        if (nxt < nchTotal)
            prefetch_chunk(sWb + (nxt & 1) * CHUNKW, gw + (size_t)nxt * 4096,
                           (nxt == nchTotal - 1) ? lastRows : 32, tid);
        else
            commit_empty();
        wait1();
        __syncthreads();
        chunk_mma<32>(sWb + (ci & 1) * CHUNKW, sA, lda, cc * 32, acc,
                      lrow, lcol8, mr0, nc0);
        ci++;
        __syncthreads();
    }
    return ci;
}

__device__ __forceinline__ void epi_silu(const float (&acc)[8][4], const float* sb,
                                         __nv_bfloat16* s_A, int r, int c,
                                         int mr0, int nc0)
{
#pragma unroll
    for (int nt = 0; nt < 8; nt++) {
        int col = nc0 + nt * 8 + 2 * c;
        float b0 = sb[col], b1 = sb[col + 1];
        *(__nv_bfloat162*)(s_A + (mr0 + r) * SA + col) =
            __floats2bfloat162_rn(siluf(acc[nt][0] + b0), siluf(acc[nt][1] + b1));
        *(__nv_bfloat162*)(s_A + (mr0 + r + 8) * SA + col) =
            __floats2bfloat162_rn(siluf(acc[nt][2] + b0), siluf(acc[nt][3] + b1));
    }
}

// ---------------- weight packing ----------------
__global__ void k_prep(const float* __restrict__ W_node, const float* __restrict__ fc1,
                       const float* __restrict__ fc2, const float* __restrict__ fc3,
                       const float* __restrict__ W_sh, const float* __restrict__ aW1,
                       const float* __restrict__ aW2, const float* __restrict__ aW3)
{
    int i = blockIdx.x * blockDim.x + threadIdx.x;
    int row = i >> 7, col = i & 127;
    if (i < 256 * 128) {
        float v = (row < 128) ? aW1[row * 128 + col] : W_node[(row - 128) * 128 + col];
        g_wnp[i] = __float2bfloat16(v);
    }
    if (i < 160 * 128) {
        float v = (row < 32) ? aW1[(128 + row) * 128 + col] : aW2[(row - 32) * 128 + col];
        g_watt[i] = __float2bfloat16(v);
    }
    if (i < 304 * 128) {
        float v;
        if (row < 32)       v = fc1[row * 128 + col];
        else if (row < 160) v = fc2[(row - 32) * 128 + col];
        else if (row < 288) v = fc3[(row - 160) * 128 + col];
        else                v = W_sh[(row - 288) * 128 + col];
        g_wmsg[i] = __float2bfloat16(v);
    }
    if (i < 128 * 8) g_w3[i] = __float2bfloat16(aW3[i]);
}

__global__ void k_init()
{
    int i = blockIdx.x * blockDim.x + threadIdx.x;
    int stride = gridDim.x * blockDim.x;
    for (int j = i; j < NN * DD; j += stride) g_agg[j] = 0.f;
    if (i < NH) g_sum[i] = 0.f;
}

// ---------------- node projections: P1, P2, XW ----------------
__global__ void __launch_bounds__(256, 3)
k_nodeproj(const float* __restrict__ nf)
{
    extern __shared__ char smem[];
    __nv_bfloat16* s_A  = (__nv_bfloat16*)smem;             // 21504
    __nv_bfloat16* s_Wb = (__nv_bfloat16*)(smem + 21504);   // 17408

    const int tid = threadIdx.x, lane = tid & 31, wid = tid >> 5;
    const int r = lane >> 2, c = lane & 3;
    const int lrow = lane & 15, lcol8 = (lane >> 1) & 8;
    const int mr0 = (wid & 3) * 16, nc0 = (wid >> 2) * 64;
    const int n0 = blockIdx.x * 64;

    prefetch_chunk(s_Wb, g_wnp, 32, tid);

#pragma unroll
    for (int i = 0; i < 8; i++) {
        int rr = wid * 8 + i;
        int n = n0 + rr; if (n >= NN) n = NN - 1;
        const float4 v = *(const float4*)(nf + (size_t)n * DD + lane * 4);
        *(__nv_bfloat162*)(s_A + rr * SA + lane * 4)     = __floats2bfloat162_rn(v.x, v.y);
        *(__nv_bfloat162*)(s_A + rr * SA + lane * 4 + 2) = __floats2bfloat162_rn(v.z, v.w);
    }

    float acc[8][4];
    clr(acc);
    int ci = pipe_gemm(0, 2, 8, 32, g_wnp, s_Wb, s_A, SA, acc, tid, lrow, lcol8, mr0, nc0);
#pragma unroll
    for (int nt = 0; nt < 8; nt++) {
        int col = nc0 + nt * 8 + 2 * c;
        int row0 = n0 + mr0 + r, row1 = row0 + 8;
        if (row0 < NN) *(__nv_bfloat162*)(g_P1 + (size_t)row0 * DD + col) =
            __floats2bfloat162_rn(acc[nt][0], acc[nt][1]);
        if (row1 < NN) *(__nv_bfloat162*)(g_P1 + (size_t)row1 * DD + col) =
            __floats2bfloat162_rn(acc[nt][2], acc[nt][3]);
    }
    clr(acc);
    ci = pipe_gemm(ci, 2, 8, 32, g_wnp, s_Wb, s_A, SA, acc, tid, lrow, lcol8, mr0, nc0);
#pragma unroll
    for (int nt = 0; nt < 8; nt++) {
        int col = nc0 + nt * 8 + 2 * c;
        int row0 = n0 + mr0 + r, row1 = row0 + 8;
        if (row0 < NN) *(__nv_bfloat162*)(g_P2 + (size_t)row0 * DD + col) =
            __floats2bfloat162_rn(acc[nt][0], acc[nt][1]);
        if (row1 < NN) *(__nv_bfloat162*)(g_P2 + (size_t)row1 * DD + col) =
            __floats2bfloat162_rn(acc[nt][2], acc[nt][3]);
    }
    clr(acc);
    ci = pipe_gemm(ci, 4, 8, 32, g_wnp, s_Wb, s_A, SA, acc, tid, lrow, lcol8, mr0, nc0);
#pragma unroll
    for (int nt = 0; nt < 8; nt++) {
        int col = nc0 + nt * 8 + 2 * c;
        int row0 = n0 + mr0 + r, row1 = row0 + 8;
        if (row0 < NN) *(__nv_bfloat162*)(g_XW + (size_t)row0 * DD + col) =
            __floats2bfloat162_rn(acc[nt][0], acc[nt][1]);
        if (row1 < NN) *(__nv_bfloat162*)(g_XW + (size_t)row1 * DD + col) =
            __floats2bfloat162_rn(acc[nt][2], acc[nt][3]);
    }
}

// ---------------- K1: attention -> exp(logits) ----------------
// smem: s_A 21504 | s_Wb 17408 | s_pd 17408 | s_ea 5120 | s_w3 2048 |
//       s_bias 1024 | s_ab3 32 | src 256 | dst 256 => 65056
__global__ void __launch_bounds__(256, 3)
k_att(const float* __restrict__ edge_attr,
      const float* __restrict__ ab1, const float* __restrict__ ab2,
      const float* __restrict__ ab3, const int* __restrict__ edge_index)
{
    extern __shared__ char smem[];
    __nv_bfloat16* s_A  = (__nv_bfloat16*)smem;                 // 21504
    __nv_bfloat16* s_Wb = (__nv_bfloat16*)(smem + 21504);       // 17408
    __nv_bfloat16* s_pd = (__nv_bfloat16*)(smem + 38912);       // 17408
    __nv_bfloat16* s_ea = (__nv_bfloat16*)(smem + 56320);       // 5120
    __nv_bfloat16* s_w3 = (__nv_bfloat16*)(smem + 61440);       // 2048
    float* s_bias = (float*)(smem + 63488);                     // 1024
    float* s_ab3  = (float*)(smem + 64512);                     // 32
    int*   s_src  = (int*)(smem + 64544);                       // 256
    int*   s_dst  = (int*)(smem + 64800);                       // 256

    const int tid = threadIdx.x, lane = tid & 31, wid = tid >> 5;
    const int r = lane >> 2, c = lane & 3;
    const int lrow = lane & 15, lcol8 = (lane >> 1) & 8;
    const int mr0 = (wid & 3) * 16, nc0 = (wid >> 2) * 64;
    const int e0 = blockIdx.x * TE;

    prefetch_chunk(s_Wb, g_watt, 32, tid);

    if (tid < TE) {
        s_src[tid] = edge_index[e0 + tid];
        s_dst[tid] = edge_index[EE + e0 + tid];
    }
    if (tid < 128) {
        s_bias[tid]       = ab1[tid];
        s_bias[128 + tid] = ab2[tid];
    }
    if (tid < NH) s_ab3[tid] = ab3[tid];
    ((uint2*)s_w3)[tid] = ((const uint2*)g_w3)[tid];   // 2048 B

    for (int idx = tid; idx < TE * 8; idx += 256) {
        int rr = idx >> 3, cc = (idx & 7) << 2;
        const float4 v = *(const float4*)(edge_attr + (size_t)(e0 + rr) * 32 + cc);
        *(__nv_bfloat162*)(s_ea + rr * SEA + cc)     = __floats2bfloat162_rn(v.x, v.y);
        *(__nv_bfloat162*)(s_ea + rr * SEA + cc + 2) = __floats2bfloat162_rn(v.z, v.w);
    }
    __syncthreads();
    // gather P1[src] + P2[dst] -> s_pd (warp-private rows)
#pragma unroll
    for (int i = 0; i < 8; i++) {
        int rr = wid * 8 + i;
        int s = s_src[rr], d = s_dst[rr];
        __nv_bfloat162 a0 = *(const __nv_bfloat162*)(g_P1 + (size_t)s * DD + lane * 4);
        __nv_bfloat162 a1 = *(const __nv_bfloat162*)(g_P1 + (size_t)s * DD + lane * 4 + 2);
        __nv_bfloat162 b0 = *(const __nv_bfloat162*)(g_P2 + (size_t)d * DD + lane * 4);
        __nv_bfloat162 b1 = *(const __nv_bfloat162*)(g_P2 + (size_t)d * DD + lane * 4 + 2);
        float2 f0 = __bfloat1622float2(a0), f1 = __bfloat1622float2(b0);
        float2 f2 = __bfloat1622float2(a1), f3 = __bfloat1622float2(b1);
        *(__nv_bfloat162*)(s_pd + rr * PS + lane * 4) =
            __floats2bfloat162_rn(f0.x + f1.x, f0.y + f1.y);
        *(__nv_bfloat162*)(s_pd + rr * PS + lane * 4 + 2) =
            __floats2bfloat162_rn(f2.x + f3.x, f2.y + f3.y);
    }

    float acc[8][4];
    // layer1: ea @ aW1_e (chunk 0), epilogue adds pd + ab1
    clr(acc);
    int ci = pipe_gemm(0, 1, 5, 32, g_watt, s_Wb, s_ea, SEA, acc, tid, lrow, lcol8, mr0, nc0);
#pragma unroll
    for (int nt = 0; nt < 8; nt++) {
        int col = nc0 + nt * 8 + 2 * c;
        float b0 = s_bias[col], b1 = s_bias[col + 1];
        float2 p0 = __bfloat1622float2(*(const __nv_bfloat162*)(s_pd + (mr0 + r) * PS + col));
        float2 p1 = __bfloat1622float2(*(const __nv_bfloat162*)(s_pd + (mr0 + r + 8) * PS + col));
        *(__nv_bfloat162*)(s_A + (mr0 + r) * SA + col) = __floats2bfloat162_rn(
            siluf(acc[nt][0] + p0.x + b0), siluf(acc[nt][1] + p0.y + b1));
        *(__nv_bfloat162*)(s_A + (mr0 + r + 8) * SA + col) = __floats2bfloat162_rn(
            siluf(acc[nt][2] + p1.x + b0), siluf(acc[nt][3] + p1.y + b1));
    }

    // layer2: aW2 (chunks 1-4)
    clr(acc);
    ci = pipe_gemm(ci, 4, 5, 32, g_watt, s_Wb, s_A, SA, acc, tid, lrow, lcol8, mr0, nc0);
    epi_silu(acc, s_bias + 128, s_A, r, c, mr0, nc0);
    __syncthreads();

    // logit layer as MMA: warps 0-3 cover 64 rows x 8 heads; store exp(logit)
    if (wid < 4) {
        float la[4] = {0.f, 0.f, 0.f, 0.f};
        unsigned w3b = (unsigned)__cvta_generic_to_shared(s_w3);
#pragma unroll
        for (int k0 = 0; k0 < 128; k0 += 16) {
            unsigned a[4];
            ldsm4(a, (unsigned)__cvta_generic_to_shared(
                         s_A + (mr0 + lrow) * SA + k0 + lcol8));
            unsigned b0, b1;
            ldsm2t(b0, b1, w3b + (unsigned)((k0 + lrow) * 8 * 2));
            mma16(la, a, b0, b1);
        }
        float h0 = s_ab3[2 * c], h1 = s_ab3[2 * c + 1];
        *(float2*)(g_a + (size_t)(e0 + mr0 + r) * NH + 2 * c) =
            make_float2(__expf(la[0] + h0), __expf(la[1] + h1));
        *(float2*)(g_a + (size_t)(e0 + mr0 + r + 8) * NH + 2 * c) =
            make_float2(__expf(la[2] + h0), __expf(la[3] + h1));
    }
}

// ---------------- K2: per-head sum of exp values (pure sum) ----------------
__global__ void k_sumexp()
{
    __shared__ float s_sum[NH];
    if (threadIdx.x < NH) s_sum[threadIdx.x] = 0.f;
    __syncthreads();
    float loc[NH];
#pragma unroll
    for (int h = 0; h < NH; h++) loc[h] = 0.f;
    for (int e = blockIdx.x * blockDim.x + threadIdx.x; e < EE; e += gridDim.x * blockDim.x) {
        const float4 a0 = *(const float4*)(g_a + (size_t)e * NH);
        const float4 a1 = *(const float4*)(g_a + (size_t)e * NH + 4);
        loc[0] += a0.x; loc[1] += a0.y; loc[2] += a0.z; loc[3] += a0.w;
        loc[4] += a1.x; loc[5] += a1.y; loc[6] += a1.z; loc[7] += a1.w;
    }
#pragma unroll
    for (int h = 0; h < NH; h++) atomicAdd(&s_sum[h], loc[h]);
    __syncthreads();
    if (threadIdx.x < NH) atomicAdd(&g_sum[threadIdx.x], s_sum[threadIdx.x]);
}

// ---------------- K3: message MLP + weighted scatter ----------------
__global__ void __launch_bounds__(256, 3)
k_msg(const float* __restrict__ edge_attr, const float* __restrict__ edge_sh,
      const float* __restrict__ b1, const float* __restrict__ b2,
      const float* __restrict__ b3, const int* __restrict__ edge_index)
{
    extern __shared__ char smem[];
    __nv_bfloat16* s_A  = (__nv_bfloat16*)smem;                 // 21504
    __nv_bfloat16* s_Wb = (__nv_bfloat16*)(smem + 21504);       // 17408
    __nv_bfloat16* s_xw = (__nv_bfloat16*)(smem + 38912);       // 17408
    __nv_bfloat16* s_sh = (__nv_bfloat16*)(smem + 56320);       // 3072
    __nv_bfloat16* s_ea = (__nv_bfloat16*)(smem + 59392);       // 5120
    float* s_bias = (float*)(smem + 64512);                     // 1536
    float* s_wt   = (float*)(smem + 66048);                     // 256
    int*   s_src  = (int*)(smem + 66304);                       // 256
    int*   s_dst  = (int*)(smem + 66560);                       // 256
    float* s_ish  = (float*)(smem + 66816);                     // 32

    const int tid = threadIdx.x, lane = tid & 31, wid = tid >> 5;
    const int r = lane >> 2, c = lane & 3;
    const int lrow = lane & 15, lcol8 = (lane >> 1) & 8;
    const int mr0 = (wid & 3) * 16, nc0 = (wid >> 2) * 64;
    const int e0 = blockIdx.x * TE;

    prefetch_chunk(s_Wb, g_wmsg, 32, tid);

    if (tid < TE) {
        s_src[tid] = edge_index[e0 + tid];
        s_dst[tid] = edge_index[EE + e0 + tid];
    }
    if (tid < 128) {
        s_bias[tid]       = b1[tid];
        s_bias[128 + tid] = b2[tid];
        s_bias[256 + tid] = b3[tid];
    }
    if (tid < NH) s_ish[tid] = 0.125f / g_sum[tid];
    for (int idx = tid; idx < TE * 4; idx += 256) {
        int rr = idx >> 2, cc = (idx & 3) << 2;
        const float4 v = *(const float4*)(edge_sh + (size_t)(e0 + rr) * 16 + cc);
        *(__nv_bfloat162*)(s_sh + rr * SSH + cc)     = __floats2bfloat162_rn(v.x, v.y);
        *(__nv_bfloat162*)(s_sh + rr * SSH + cc + 2) = __floats2bfloat162_rn(v.z, v.w);
    }
    for (int idx = tid; idx < TE * 8; idx += 256) {
        int rr = idx >> 3, cc = (idx & 7) << 2;
        const float4 v = *(const float4*)(edge_attr + (size_t)(e0 + rr) * 32 + cc);
        *(__nv_bfloat162*)(s_ea + rr * SEA + cc)     = __floats2bfloat162_rn(v.x, v.y);
        *(__nv_bfloat162*)(s_ea + rr * SEA + cc + 2) = __floats2bfloat162_rn(v.z, v.w);
    }
    __syncthreads();
    // per-edge softmax-mean weight from precomputed exp values (no expf)
    if (tid < TE) {
        const float4 ev0 = *(const float4*)(g_a + (size_t)(e0 + tid) * NH);
        const float4 ev1 = *(const float4*)(g_a + (size_t)(e0 + tid) * NH + 4);
        s_wt[tid] = ev0.x * s_ish[0] + ev0.y * s_ish[1] + ev0.z * s_ish[2] + ev0.w * s_ish[3]
                  + ev1.x * s_ish[4] + ev1.y * s_ish[5] + ev1.z * s_ish[6] + ev1.w * s_ish[7];
    }
    // gather XW[src] -> s_xw (warp-private rows, bf16 copy)
#pragma unroll
    for (int i = 0; i < 8; i++) {
        int rr = wid * 8 + i;
        int s = s_src[rr];
        const uint2 v = *(const uint2*)(g_XW + (size_t)s * DD + lane * 4);
        *(uint2*)(s_xw + rr * XS + lane * 4) = v;
    }

    float acc[8][4];
    // fc1 (chunk 0, A = s_ea)
    clr(acc);
    int ci = pipe_gemm(0, 1, 10, 16, g_wmsg, s_Wb, s_ea, SEA, acc, tid, lrow, lcol8, mr0, nc0);
    epi_silu(acc, s_bias, s_A, r, c, mr0, nc0);

    // fc2 (chunks 1-4)
    clr(acc);
    ci = pipe_gemm(ci, 4, 10, 16, g_wmsg, s_Wb, s_A, SA, acc, tid, lrow, lcol8, mr0, nc0);
    epi_silu(acc, s_bias + 128, s_A, r, c, mr0, nc0);

    // fc3 (chunks 5-8) -> scale = fc3 + b3 into s_A (frag-owned)
    clr(acc);
    ci = pipe_gemm(ci, 4, 10, 16, g_wmsg, s_Wb, s_A, SA, acc, tid, lrow, lcol8, mr0, nc0);
#pragma unroll
    for (int nt = 0; nt < 8; nt++) {
        int col = nc0 + nt * 8 + 2 * c;
        float b0 = s_bias[256 + col], b1v = s_bias[256 + col + 1];
        *(__nv_bfloat162*)(s_A + (mr0 + r) * SA + col) =
            __floats2bfloat162_rn(acc[nt][0] + b0, acc[nt][1] + b1v);
        *(__nv_bfloat162*)(s_A + (mr0 + r + 8) * SA + col) =
            __floats2bfloat162_rn(acc[nt][2] + b0, acc[nt][3] + b1v);
    }

    // W_sh (chunk 9, 16 rows, A = s_sh)
    clr(acc);
    commit_empty();
    wait1();
    __syncthreads();
    chunk_mma<16>(s_Wb + (ci & 1) * CHUNKW, s_sh, SSH, 0, acc, lrow, lcol8, mr0, nc0);

    // msg = silu(xw * scale + shp) * wt -> s_xw
#pragma unroll
    for (int nt = 0; nt < 8; nt++) {
        int col = nc0 + nt * 8 + 2 * c;
        float w0 = s_wt[mr0 + r], w1 = s_wt[mr0 + r + 8];
        float2 sc0 = __bfloat1622float2(*(__nv_bfloat162*)(s_A + (mr0 + r) * SA + col));
        float2 sc1 = __bfloat1622float2(*(__nv_bfloat162*)(s_A + (mr0 + r + 8) * SA + col));
        float2 xw0 = __bfloat1622float2(*(__nv_bfloat162*)(s_xw + (mr0 + r) * XS + col));
        float2 xw1 = __bfloat1622float2(*(__nv_bfloat162*)(s_xw + (mr0 + r + 8) * XS + col));
        *(__nv_bfloat162*)(s_xw + (mr0 + r) * XS + col) = __floats2bfloat162_rn(
            siluf(xw0.x * sc0.x + acc[nt][0]) * w0, siluf(xw0.y * sc0.y + acc[nt][1]) * w0);
        *(__nv_bfloat162*)(s_xw + (mr0 + r + 8) * XS + col) = __floats2bfloat162_rn(
            siluf(xw1.x * sc1.x + acc[nt][2]) * w1, siluf(xw1.y * sc1.y + acc[nt][3]) * w1);
    }
    __syncthreads();

#pragma unroll
    for (int i = 0; i < 8; i++) {
        int rr = wid * 8 + i;
        int d = s_dst[rr];
        __nv_bfloat162 p0 = *(__nv_bfloat162*)(s_xw + rr * XS + lane * 4);
        __nv_bfloat162 p1 = *(__nv_bfloat162*)(s_xw + rr * XS + lane * 4 + 2);
        float2 f0 = __bfloat1622float2(p0), f1 = __bfloat1622float2(p1);
        float* p = g_agg + (size_t)d * DD + lane * 4;
        atomicAdd(p + 0, f0.x);
        atomicAdd(p + 1, f0.y);
        atomicAdd(p + 2, f1.x);
        atomicAdd(p + 3, f1.y);
    }
}

// ---------------- K4: out = LN(nf + agg @ W_out) ----------------
__global__ void k_node(const float* __restrict__ nf, const float* __restrict__ W_out,
                       float* __restrict__ out)
{
    extern __shared__ float smemf[];
    float* sW    = smemf;
    float* s_row = sW + 128 * 128;
    const int tid = threadIdx.x, tx = tid & 31, w = tid >> 5;
    for (int idx = tid; idx < 128 * 32; idx += 256) {
        int rr = idx >> 5, cc = (idx & 31) << 2;
        *(float4*)(sW + rr * 128 + cc) = *(const float4*)(W_out + (size_t)rr * 128 + cc);
    }
    __syncthreads();
    for (int n = blockIdx.x * 8 + w; n < NN; n += gridDim.x * 8) {
        float4 av = *(const float4*)(g_agg + (size_t)n * DD + tx * 4);
        __syncwarp();
        *(float4*)(s_row + w * 128 + tx * 4) = av;
        __syncwarp();
        float a0 = 0.f, a1 = 0.f, a2 = 0.f, a3 = 0.f;
#pragma unroll 8
        for (int k = 0; k < 128; k++) {
            float a = s_row[w * 128 + k];
            const float4 wv = *(const float4*)(sW + k * 128 + tx * 4);
            a0 += a * wv.x; a1 += a * wv.y; a2 += a * wv.z; a3 += a * wv.w;
        }
        const float4 x = *(const float4*)(nf + (size_t)n * DD + tx * 4);
        float v0 = x.x + a0, v1 = x.y + a1, v2 = x.z + a2, v3 = x.w + a3;
        float s = v0 + v1 + v2 + v3;
#pragma unroll
        for (int o = 16; o > 0; o >>= 1) s += __shfl_xor_sync(0xffffffffu, s, o);
        float mu = s * (1.f / 128.f);
        float d0 = v0 - mu, d1 = v1 - mu, d2 = v2 - mu, d3 = v3 - mu;
        float q = d0 * d0 + d1 * d1 + d2 * d2 + d3 * d3;
#pragma unroll
        for (int o = 16; o > 0; o >>= 1) q += __shfl_xor_sync(0xffffffffu, q, o);
        float rs = rsqrtf(q * (1.f / 128.f) + 1e-5f);
        float4 o4 = make_float4(d0 * rs, d1 * rs, d2 * rs, d3 * rs);
        *(float4*)(out + (size_t)n * DD + tx * 4) = o4;
    }
}

extern "C" void kernel_launch(void* const* d_in, const int* in_sizes, int n_in,
                              void* d_out, int out_size)
{
    const float* nf        = (const float*)d_in[0];
    const float* edge_attr = (const float*)d_in[1];
    const float* edge_sh   = (const float*)d_in[2];
    const float* W_node    = (const float*)d_in[3];
    const float* fc1 = (const float*)d_in[4];
    const float* b1  = (const float*)d_in[5];
    const float* fc2 = (const float*)d_in[6];
    const float* b2  = (const float*)d_in[7];
    const float* fc3 = (const float*)d_in[8];
    const float* b3  = (const float*)d_in[9];
    const float* W_sh = (const float*)d_in[10];
    const float* aW1 = (const float*)d_in[11];
    const float* ab1 = (const float*)d_in[12];
    const float* aW2 = (const float*)d_in[13];
    const float* ab2 = (const float*)d_in[14];
    const float* aW3 = (const float*)d_in[15];
    const float* ab3 = (const float*)d_in[16];
    const float* W_out = (const float*)d_in[17];
    const int* edge_index = (const int*)d_in[18];
    float* out = (float*)d_out;

    const int SMEM_NP   = 38912;
    const int SMEM_ATT  = 65056;
    const int SMEM_MSG  = 66848;
    const int SMEM_NODE = (128 * 128 + 8 * 128) * 4;
    cudaFuncSetAttribute(k_nodeproj, cudaFuncAttributeMaxDynamicSharedMemorySize, SMEM_NP);
    cudaFuncSetAttribute(k_att,  cudaFuncAttributeMaxDynamicSharedMemorySize, SMEM_ATT);
    cudaFuncSetAttribute(k_msg,  cudaFuncAttributeMaxDynamicSharedMemorySize, SMEM_MSG);
    cudaFuncSetAttribute(k_node, cudaFuncAttributeMaxDynamicSharedMemorySize, SMEM_NODE);

    k_prep<<<152, 256>>>(W_node, fc1, fc2, fc3, W_sh, aW1, aW2, aW3);
    k_init<<<2048, 256>>>();
    k_nodeproj<<<(NN + 63) / 64, 256, SMEM_NP>>>(nf);
    k_att<<<EE / TE, 256, SMEM_ATT>>>(edge_attr, ab1, ab2, ab3, edge_index);
    k_sumexp<<<1024, 256>>>();
    k_msg<<<EE / TE, 256, SMEM_MSG>>>(edge_attr, edge_sh, b1, b2, b3, edge_index);
    k_node<<<296, 256, SMEM_NODE>>>(nf, W_out, out);
}

// round 10
// speedup vs baseline: 3.0955x; 1.0700x over previous
#include <cuda_runtime.h>
#include <cuda_bf16.h>

#define NN 50000
#define EE 800000
#define DD 128
#define NH 8
#define TE 64
#define SA 168
#define WS2 136
#define SSH 24
#define SEA 40
#define XS 136
#define PS 136
#define CHUNKW (32 * WS2)

__device__ float    g_a[(size_t)EE * NH];     // exp(logit) per edge/head
__device__ float    g_agg[(size_t)NN * DD];
__device__ float    g_sum[NH];
__device__ __align__(256) __nv_bfloat16 g_wnp[256 * 128];   // aW1[0:128) | W_node
__device__ __align__(256) __nv_bfloat16 g_watt[160 * 128];  // aW1[128:160) | aW2
__device__ __align__(256) __nv_bfloat16 g_wmsg[304 * 128];  // fc1|fc2|fc3|W_sh
__device__ __align__(256) __nv_bfloat16 g_w3[128 * 8];      // aW3 bf16
__device__ __align__(256) __nv_bfloat16 g_P1[(size_t)NN * DD];
__device__ __align__(256) __nv_bfloat16 g_P2[(size_t)NN * DD];
__device__ __align__(256) __nv_bfloat16 g_XW[(size_t)NN * DD];

__device__ __forceinline__ float siluf(float x) {
    float t;
    asm("tanh.approx.f32 %0, %1;" : "=f"(t) : "f"(x * 0.5f));
    return 0.5f * x * (1.f + t);
}
__device__ __forceinline__ void ldsm4(unsigned (&r)[4], unsigned addr) {
    asm volatile("ldmatrix.sync.aligned.m8n8.x4.shared.b16 {%0,%1,%2,%3}, [%4];"
                 : "=r"(r[0]), "=r"(r[1]), "=r"(r[2]), "=r"(r[3]) : "r"(addr));
}
__device__ __forceinline__ void ldsm4t(unsigned* r, unsigned addr) {
    asm volatile("ldmatrix.sync.aligned.m8n8.x4.trans.shared.b16 {%0,%1,%2,%3}, [%4];"
                 : "=r"(r[0]), "=r"(r[1]), "=r"(r[2]), "=r"(r[3]) : "r"(addr));
}
__device__ __forceinline__ void ldsm2t(unsigned& r0, unsigned& r1, unsigned addr) {
    asm volatile("ldmatrix.sync.aligned.m8n8.x2.trans.shared.b16 {%0,%1}, [%2];"
                 : "=r"(r0), "=r"(r1) : "r"(addr));
}
__device__ __forceinline__ void mma16(float (&d)[4], const unsigned (&a)[4],
                                      unsigned b0, unsigned b1) {
    asm volatile(
        "mma.sync.aligned.m16n8k16.row.col.f32.bf16.bf16.f32 "
        "{%0,%1,%2,%3}, {%4,%5,%6,%7}, {%8,%9}, {%0,%1,%2,%3};\n"
        : "+f"(d[0]), "+f"(d[1]), "+f"(d[2]), "+f"(d[3])
        : "r"(a[0]), "r"(a[1]), "r"(a[2]), "r"(a[3]), "r"(b0), "r"(b1));
}
__device__ __forceinline__ unsigned cvta(const void* p) {
    return (unsigned)__cvta_generic_to_shared(p);
}
__device__ __forceinline__ unsigned packbf(float a, float b) {
    __nv_bfloat162 v = __floats2bfloat162_rn(a, b);
    return *(unsigned*)&v;
}
__device__ __forceinline__ void clr16(float (&acc)[16][4]) {
#pragma unroll
    for (int i = 0; i < 16; i++)
#pragma unroll
        for (int j = 0; j < 4; j++) acc[i][j] = 0.f;
}
__device__ __forceinline__ void clr8(float (&acc)[8][4]) {
#pragma unroll
    for (int i = 0; i < 8; i++)
#pragma unroll
        for (int j = 0; j < 4; j++) acc[i][j] = 0.f;
}

__device__ __forceinline__ void prefetch_chunk(__nv_bfloat16* sbuf,
        const __nv_bfloat16* __restrict__ gsrc, int nrows, int tid, int nthr)
{
    for (int idx = tid; idx < nrows * 16; idx += nthr) {
        int row = idx >> 4, seg = idx & 15;
        unsigned d = cvta(sbuf + row * WS2) + seg * 16;
        const char* s = (const char*)(gsrc + (size_t)row * 128) + seg * 16;
        asm volatile("cp.async.cg.shared.global [%0], [%1], 16;" :: "r"(d), "l"(s));
    }
    asm volatile("cp.async.commit_group;" ::: "memory");
}
__device__ __forceinline__ void commit_empty() {
    asm volatile("cp.async.commit_group;" ::: "memory");
}
__device__ __forceinline__ void wait1() {
    asm volatile("cp.async.wait_group 1;" ::: "memory");
}

// ===== 4-warp chain-style tile: warp = 16 rows x 128 cols, acc[16][4] =====
template<int NK>
__device__ __forceinline__ void cmma_s(const __nv_bfloat16* sW,
        const __nv_bfloat16* sA, int lda, float (&acc)[16][4],
        int lrow, int lcol8, int mr0)
{
#pragma unroll
    for (int ks = 0; ks < NK / 16; ks++) {
        unsigned a[4];
        ldsm4(a, cvta(sA + (mr0 + lrow) * lda + ks * 16 + lcol8));
#pragma unroll
        for (int np = 0; np < 8; np++) {
            unsigned bb[4];
            ldsm4t(bb, cvta(sW + (ks * 16 + lrow) * WS2 + np * 16 + lcol8));
            mma16(acc[2 * np], a, bb[0], bb[1]);
            mma16(acc[2 * np + 1], a, bb[2], bb[3]);
        }
    }
}
__device__ __forceinline__ void cmma_r(const __nv_bfloat16* sW,
        const unsigned* aP, int cc, float (&acc)[16][4], int lrow, int lcol8)
{
#pragma unroll
    for (int ks = 0; ks < 2; ks++) {
        const int kg = 2 * cc + ks;
        unsigned a[4] = {aP[4 * kg], aP[4 * kg + 1], aP[4 * kg + 2], aP[4 * kg + 3]};
#pragma unroll
        for (int np = 0; np < 8; np++) {
            unsigned bb[4];
            ldsm4t(bb, cvta(sW + (ks * 16 + lrow) * WS2 + np * 16 + lcol8));
            mma16(acc[2 * np], a, bb[0], bb[1]);
            mma16(acc[2 * np + 1], a, bb[2], bb[3]);
        }
    }
}
// one K=32 chunk, A from shared
__device__ __forceinline__ int pipe_s32(int ci, int nchTot, int lastRows,
        const __nv_bfloat16* __restrict__ gw, __nv_bfloat16* sWb,
        const __nv_bfloat16* sA, int lda, float (&acc)[16][4],
        int tid, int lrow, int lcol8, int mr0)
{
    int nxt = ci + 1;
    if (nxt < nchTot)
        prefetch_chunk(sWb + (nxt & 1) * CHUNKW, gw + (size_t)nxt * 4096,
                       (nxt == nchTot - 1) ? lastRows : 32, tid, 128);
    else commit_empty();
    wait1();
    __syncthreads();
    cmma_s<32>(sWb + (ci & 1) * CHUNKW, sA, lda, acc, lrow, lcol8, mr0);
    __syncthreads();
    return ci + 1;
}
// nc K=32 chunks, A from registers
__device__ __forceinline__ int pipe_r(int ci, int nc, int nchTot, int lastRows,
        const __nv_bfloat16* __restrict__ gw, __nv_bfloat16* sWb,
        const unsigned* aP, float (&acc)[16][4],
        int tid, int lrow, int lcol8)
{
    for (int cc = 0; cc < nc; cc++) {
        int nxt = ci + 1;
        if (nxt < nchTot)
            prefetch_chunk(sWb + (nxt & 1) * CHUNKW, gw + (size_t)nxt * 4096,
                           (nxt == nchTot - 1) ? lastRows : 32, tid, 128);
        else commit_empty();
        wait1();
        __syncthreads();
        cmma_r(sWb + (ci & 1) * CHUNKW, aP, cc, acc, lrow, lcol8);
        ci++;
        __syncthreads();
    }
    return ci;
}

// ===== 8-warp tile helpers (nodeproj only; 256 threads, acc[8][4]) =====
template<int NK>
__device__ __forceinline__ void chunk_mma8(const __nv_bfloat16* sW,
        const __nv_bfloat16* sA, int lda, int kc, float (&acc)[8][4],
        int lrow, int lcol8, int mr0, int nc0)
{
#pragma unroll
    for (int k0 = 0; k0 < NK; k0 += 16) {
        unsigned a[4];
        ldsm4(a, cvta(sA + (mr0 + lrow) * lda + kc + k0 + lcol8));
        unsigned b[16];
#pragma unroll
        for (int np = 0; np < 4; np++)
            ldsm4t(b + np * 4, cvta(sW + (k0 + lrow) * WS2 + nc0 + np * 16 + lcol8));
#pragma unroll
        for (int nt = 0; nt < 8; nt++)
            mma16(acc[nt], a, b[(nt >> 1) * 4 + (nt & 1) * 2],
                              b[(nt >> 1) * 4 + (nt & 1) * 2 + 1]);
    }
}
__device__ __forceinline__ int pipe8(int ci, int nc, int nchTot, int lastRows,
        const __nv_bfloat16* __restrict__ gw, __nv_bfloat16* sWb,
        const __nv_bfloat16* sA, int lda, float (&acc)[8][4],
        int tid, int lrow, int lcol8, int mr0, int nc0)
{
    for (int cc = 0; cc < nc; cc++) {
        int nxt = ci + 1;
        if (nxt < nchTot)
            prefetch_chunk(sWb + (nxt & 1) * CHUNKW, gw + (size_t)nxt * 4096,
                           (nxt == nchTot - 1) ? lastRows : 32, tid, 256);
        else commit_empty();
        wait1();
        __syncthreads();
        chunk_mma8<32>(sWb + (ci & 1) * CHUNKW, sA, lda, cc * 32, acc,
                       lrow, lcol8, mr0, nc0);
        ci++;
        __syncthreads();
    }
    return ci;
}

// ---------------- weight packing ----------------
__global__ void k_prep(const float* __restrict__ W_node, const float* __restrict__ fc1,
                       const float* __restrict__ fc2, const float* __restrict__ fc3,
                       const float* __restrict__ W_sh, const float* __restrict__ aW1,
                       const float* __restrict__ aW2, const float* __restrict__ aW3)
{
    int i = blockIdx.x * blockDim.x + threadIdx.x;
    int row = i >> 7, col = i & 127;
    if (i < 256 * 128) {
        float v = (row < 128) ? aW1[row * 128 + col] : W_node[(row - 128) * 128 + col];
        g_wnp[i] = __float2bfloat16(v);
    }
    if (i < 160 * 128) {
        float v = (row < 32) ? aW1[(128 + row) * 128 + col] : aW2[(row - 32) * 128 + col];
        g_watt[i] = __float2bfloat16(v);
    }
    if (i < 304 * 128) {
        float v;
        if (row < 32)       v = fc1[row * 128 + col];
        else if (row < 160) v = fc2[(row - 32) * 128 + col];
        else if (row < 288) v = fc3[(row - 160) * 128 + col];
        else                v = W_sh[(row - 288) * 128 + col];
        g_wmsg[i] = __float2bfloat16(v);
    }
    if (i < 128 * 8) g_w3[i] = __float2bfloat16(aW3[i]);
}

__global__ void k_init()
{
    int i = blockIdx.x * blockDim.x + threadIdx.x;
    int stride = gridDim.x * blockDim.x;
    for (int j = i; j < NN * DD; j += stride) g_agg[j] = 0.f;
    if (i < NH) g_sum[i] = 0.f;
}

// ---------------- node projections: P1, P2, XW (unchanged 8-warp style) ----------------
__global__ void __launch_bounds__(256, 3)
k_nodeproj(const float* __restrict__ nf)
{
    extern __shared__ char smem[];
    __nv_bfloat16* s_A  = (__nv_bfloat16*)smem;             // 21504
    __nv_bfloat16* s_Wb = (__nv_bfloat16*)(smem + 21504);   // 17408

    const int tid = threadIdx.x, lane = tid & 31, wid = tid >> 5;
    const int r = lane >> 2, c = lane & 3;
    const int lrow = lane & 15, lcol8 = (lane >> 1) & 8;
    const int mr0 = (wid & 3) * 16, nc0 = (wid >> 2) * 64;
    const int n0 = blockIdx.x * 64;

    prefetch_chunk(s_Wb, g_wnp, 32, tid, 256);

#pragma unroll
    for (int i = 0; i < 8; i++) {
        int rr = wid * 8 + i;
        int n = n0 + rr; if (n >= NN) n = NN - 1;
        const float4 v = *(const float4*)(nf + (size_t)n * DD + lane * 4);
        *(__nv_bfloat162*)(s_A + rr * SA + lane * 4)     = __floats2bfloat162_rn(v.x, v.y);
        *(__nv_bfloat162*)(s_A + rr * SA + lane * 4 + 2) = __floats2bfloat162_rn(v.z, v.w);
    }

    float acc[8][4];
    clr8(acc);
    int ci = pipe8(0, 2, 8, 32, g_wnp, s_Wb, s_A, SA, acc, tid, lrow, lcol8, mr0, nc0);
#pragma unroll
    for (int nt = 0; nt < 8; nt++) {
        int col = nc0 + nt * 8 + 2 * c;
        int row0 = n0 + mr0 + r, row1 = row0 + 8;
        if (row0 < NN) *(__nv_bfloat162*)(g_P1 + (size_t)row0 * DD + col) =
            __floats2bfloat162_rn(acc[nt][0], acc[nt][1]);
        if (row1 < NN) *(__nv_bfloat162*)(g_P1 + (size_t)row1 * DD + col) =
            __floats2bfloat162_rn(acc[nt][2], acc[nt][3]);
    }
    clr8(acc);
    ci = pipe8(ci, 2, 8, 32, g_wnp, s_Wb, s_A, SA, acc, tid, lrow, lcol8, mr0, nc0);
#pragma unroll
    for (int nt = 0; nt < 8; nt++) {
        int col = nc0 + nt * 8 + 2 * c;
        int row0 = n0 + mr0 + r, row1 = row0 + 8;
        if (row0 < NN) *(__nv_bfloat162*)(g_P2 + (size_t)row0 * DD + col) =
            __floats2bfloat162_rn(acc[nt][0], acc[nt][1]);
        if (row1 < NN) *(__nv_bfloat162*)(g_P2 + (size_t)row1 * DD + col) =
            __floats2bfloat162_rn(acc[nt][2], acc[nt][3]);
    }
    clr8(acc);
    ci = pipe8(ci, 4, 8, 32, g_wnp, s_Wb, s_A, SA, acc, tid, lrow, lcol8, mr0, nc0);
#pragma unroll
    for (int nt = 0; nt < 8; nt++) {
        int col = nc0 + nt * 8 + 2 * c;
        int row0 = n0 + mr0 + r, row1 = row0 + 8;
        if (row0 < NN) *(__nv_bfloat162*)(g_XW + (size_t)row0 * DD + col) =
            __floats2bfloat162_rn(acc[nt][0], acc[nt][1]);
        if (row1 < NN) *(__nv_bfloat162*)(g_XW + (size_t)row1 * DD + col) =
            __floats2bfloat162_rn(acc[nt][2], acc[nt][3]);
    }
}

// ---------------- K1: attention -> exp(logits), register-chained ----------------
// 128 threads, 4 warps; warp = 16 rows x 128 cols.
// smem: s_Wb 17408 | s_ea 5120 | s_pd 17408 | s_w3 2048 | bias 1024 | ab3 32 |
//       src 256 | dst 256 => 43552
__global__ void __launch_bounds__(128, 4)
k_att(const float* __restrict__ edge_attr,
      const float* __restrict__ ab1, const float* __restrict__ ab2,
      const float* __restrict__ ab3, const int* __restrict__ edge_index)
{
    extern __shared__ char smem[];
    __nv_bfloat16* s_Wb = (__nv_bfloat16*)smem;                 // 17408
    __nv_bfloat16* s_ea = (__nv_bfloat16*)(smem + 17408);       // 5120
    __nv_bfloat16* s_pd = (__nv_bfloat16*)(smem + 22528);       // 17408
    __nv_bfloat16* s_w3 = (__nv_bfloat16*)(smem + 39936);       // 2048
    float* s_bias = (float*)(smem + 41984);                     // 1024
    float* s_ab3  = (float*)(smem + 43008);                     // 32
    int*   s_src  = (int*)(smem + 43040);                       // 256
    int*   s_dst  = (int*)(smem + 43296);                       // 256

    const int tid = threadIdx.x, lane = tid & 31, wid = tid >> 5;
    const int r = lane >> 2, c = lane & 3;
    const int lrow = lane & 15, lcol8 = (lane >> 1) & 8;
    const int mr0 = wid * 16;
    const int e0 = blockIdx.x * TE;

    prefetch_chunk(s_Wb, g_watt, 32, tid, 128);

    if (tid < TE) {
        s_src[tid] = edge_index[e0 + tid];
        s_dst[tid] = edge_index[EE + e0 + tid];
    }
    s_bias[tid]       = ab1[tid];
    s_bias[128 + tid] = ab2[tid];
    if (tid < NH) s_ab3[tid] = ab3[tid];
    ((uint4*)s_w3)[tid] = ((const uint4*)g_w3)[tid];    // 2048 B

    for (int idx = tid; idx < TE * 8; idx += 128) {
        int rr = idx >> 3, cc = (idx & 7) << 2;
        const float4 v = *(const float4*)(edge_attr + (size_t)(e0 + rr) * 32 + cc);
        *(__nv_bfloat162*)(s_ea + rr * SEA + cc)     = __floats2bfloat162_rn(v.x, v.y);
        *(__nv_bfloat162*)(s_ea + rr * SEA + cc + 2) = __floats2bfloat162_rn(v.z, v.w);
    }
    __syncthreads();
    // gather P1[src] + P2[dst] -> s_pd (warp-private rows)
#pragma unroll
    for (int i = 0; i < 16; i++) {
        int rr = mr0 + i;
        int s = s_src[rr], d = s_dst[rr];
        __nv_bfloat162 a0 = *(const __nv_bfloat162*)(g_P1 + (size_t)s * DD + lane * 4);
        __nv_bfloat162 a1 = *(const __nv_bfloat162*)(g_P1 + (size_t)s * DD + lane * 4 + 2);
        __nv_bfloat162 b0 = *(const __nv_bfloat162*)(g_P2 + (size_t)d * DD + lane * 4);
        __nv_bfloat162 b1 = *(const __nv_bfloat162*)(g_P2 + (size_t)d * DD + lane * 4 + 2);
        float2 f0 = __bfloat1622float2(a0), f1 = __bfloat1622float2(b0);
        float2 f2 = __bfloat1622float2(a1), f3 = __bfloat1622float2(b1);
        *(__nv_bfloat162*)(s_pd + rr * PS + lane * 4) =
            __floats2bfloat162_rn(f0.x + f1.x, f0.y + f1.y);
        *(__nv_bfloat162*)(s_pd + rr * PS + lane * 4 + 2) =
            __floats2bfloat162_rn(f2.x + f3.x, f2.y + f3.y);
    }

    float acc[16][4];
    unsigned aP[32];
    // layer1: ea @ aW1_e (chunk 0)
    clr16(acc);
    int ci = pipe_s32(0, 5, 32, g_watt, s_Wb, s_ea, SEA, acc, tid, lrow, lcol8, mr0);
#pragma unroll
    for (int nt = 0; nt < 16; nt++) {
        int col = 8 * nt + 2 * c;
        float b0 = s_bias[col], b1 = s_bias[col + 1];
        float2 p0 = __bfloat1622float2(*(const __nv_bfloat162*)(s_pd + (mr0 + r) * PS + col));
        float2 p1 = __bfloat1622float2(*(const __nv_bfloat162*)(s_pd + (mr0 + r + 8) * PS + col));
        aP[2 * nt]     = packbf(siluf(acc[nt][0] + p0.x + b0), siluf(acc[nt][1] + p0.y + b1));
        aP[2 * nt + 1] = packbf(siluf(acc[nt][2] + p1.x + b0), siluf(acc[nt][3] + p1.y + b1));
    }
    // layer2: aW2 (chunks 1-4), A from registers
    clr16(acc);
    ci = pipe_r(ci, 4, 5, 32, g_watt, s_Wb, aP, acc, tid, lrow, lcol8);
#pragma unroll
    for (int nt = 0; nt < 16; nt++) {
        int col = 8 * nt + 2 * c;
        float b0 = s_bias[128 + col], b1 = s_bias[128 + col + 1];
        aP[2 * nt]     = packbf(siluf(acc[nt][0] + b0), siluf(acc[nt][1] + b1));
        aP[2 * nt + 1] = packbf(siluf(acc[nt][2] + b0), siluf(acc[nt][3] + b1));
    }
    // logit layer: K=128 from registers, B = s_w3 (n=8), all 4 warps
    float la[4] = {0.f, 0.f, 0.f, 0.f};
#pragma unroll
    for (int ks = 0; ks < 8; ks++) {
        unsigned b0, b1;
        ldsm2t(b0, b1, cvta(s_w3 + (16 * ks + lrow) * 8));
        unsigned av[4] = {aP[4 * ks], aP[4 * ks + 1], aP[4 * ks + 2], aP[4 * ks + 3]};
        mma16(la, av, b0, b1);
    }
    float h0 = s_ab3[2 * c], h1 = s_ab3[2 * c + 1];
    *(float2*)(g_a + (size_t)(e0 + mr0 + r) * NH + 2 * c) =
        make_float2(__expf(la[0] + h0), __expf(la[1] + h1));
    *(float2*)(g_a + (size_t)(e0 + mr0 + r + 8) * NH + 2 * c) =
        make_float2(__expf(la[2] + h0), __expf(la[3] + h1));
}

// ---------------- K2: per-head sum ----------------
__global__ void k_sumexp()
{
    __shared__ float s_sum[NH];
    if (threadIdx.x < NH) s_sum[threadIdx.x] = 0.f;
    __syncthreads();
    float loc[NH];
#pragma unroll
    for (int h = 0; h < NH; h++) loc[h] = 0.f;
    for (int e = blockIdx.x * blockDim.x + threadIdx.x; e < EE; e += gridDim.x * blockDim.x) {
        const float4 a0 = *(const float4*)(g_a + (size_t)e * NH);
        const float4 a1 = *(const float4*)(g_a + (size_t)e * NH + 4);
        loc[0] += a0.x; loc[1] += a0.y; loc[2] += a0.z; loc[3] += a0.w;
        loc[4] += a1.x; loc[5] += a1.y; loc[6] += a1.z; loc[7] += a1.w;
    }
#pragma unroll
    for (int h = 0; h < NH; h++) atomicAdd(&s_sum[h], loc[h]);
    __syncthreads();
    if (threadIdx.x < NH) atomicAdd(&g_sum[threadIdx.x], s_sum[threadIdx.x]);
}

// ---------------- K3: message MLP + weighted scatter, register-chained ----------------
// smem: s_Wb 17408 | s_ea 5120 | s_x 17408 | s_sh 3072 | bias 1536 | wt 256 |
//       ish 32 | src 256 | dst 256 => 45344
__global__ void __launch_bounds__(128, 4)
k_msg(const float* __restrict__ edge_attr, const float* __restrict__ edge_sh,
      const float* __restrict__ b1, const float* __restrict__ b2,
      const float* __restrict__ b3, const int* __restrict__ edge_index)
{
    extern __shared__ char smem[];
    __nv_bfloat16* s_Wb = (__nv_bfloat16*)smem;                 // 17408
    __nv_bfloat16* s_ea = (__nv_bfloat16*)(smem + 17408);       // 5120
    __nv_bfloat16* s_x  = (__nv_bfloat16*)(smem + 22528);       // 17408
    __nv_bfloat16* s_sh = (__nv_bfloat16*)(smem + 39936);       // 3072
    float* s_bias = (float*)(smem + 43008);                     // 1536
    float* s_wt   = (float*)(smem + 44544);                     // 256
    float* s_ish  = (float*)(smem + 44800);                     // 32
    int*   s_src  = (int*)(smem + 44832);                       // 256
    int*   s_dst  = (int*)(smem + 45088);                       // 256

    const int tid = threadIdx.x, lane = tid & 31, wid = tid >> 5;
    const int r = lane >> 2, c = lane & 3;
    const int lrow = lane & 15, lcol8 = (lane >> 1) & 8;
    const int mr0 = wid * 16;
    const int e0 = blockIdx.x * TE;

    prefetch_chunk(s_Wb, g_wmsg, 32, tid, 128);

    if (tid < TE) {
        s_src[tid] = edge_index[e0 + tid];
        s_dst[tid] = edge_index[EE + e0 + tid];
    }
    s_bias[tid]       = b1[tid];
    s_bias[128 + tid] = b2[tid];
    s_bias[256 + tid] = b3[tid];
    if (tid < NH) s_ish[tid] = 0.125f / g_sum[tid];
    for (int idx = tid; idx < TE * 4; idx += 128) {
        int rr = idx >> 2, cc = (idx & 3) << 2;
        const float4 v = *(const float4*)(edge_sh + (size_t)(e0 + rr) * 16 + cc);
        *(__nv_bfloat162*)(s_sh + rr * SSH + cc)     = __floats2bfloat162_rn(v.x, v.y);
        *(__nv_bfloat162*)(s_sh + rr * SSH + cc + 2) = __floats2bfloat162_rn(v.z, v.w);
    }
    for (int idx = tid; idx < TE * 8; idx += 128) {
        int rr = idx >> 3, cc = (idx & 7) << 2;
        const float4 v = *(const float4*)(edge_attr + (size_t)(e0 + rr) * 32 + cc);
        *(__nv_bfloat162*)(s_ea + rr * SEA + cc)     = __floats2bfloat162_rn(v.x, v.y);
        *(__nv_bfloat162*)(s_ea + rr * SEA + cc + 2) = __floats2bfloat162_rn(v.z, v.w);
    }
    __syncthreads();
    if (tid < TE) {   // per-edge softmax-mean weight
        const float4 ev0 = *(const float4*)(g_a + (size_t)(e0 + tid) * NH);
        const float4 ev1 = *(const float4*)(g_a + (size_t)(e0 + tid) * NH + 4);
        s_wt[tid] = ev0.x * s_ish[0] + ev0.y * s_ish[1] + ev0.z * s_ish[2] + ev0.w * s_ish[3]
                  + ev1.x * s_ish[4] + ev1.y * s_ish[5] + ev1.z * s_ish[6] + ev1.w * s_ish[7];
    }
    // gather XW[src] -> s_x (warp-private rows)
#pragma unroll
    for (int i = 0; i < 16; i++) {
        int rr = mr0 + i;
        const uint2 v = *(const uint2*)(g_XW + (size_t)s_src[rr] * DD + lane * 4);
        *(uint2*)(s_x + rr * XS + lane * 4) = v;
    }

    float acc[16][4];
    unsigned aP[32];
    // fc1 (chunk 0, K=32, A = s_ea)
    clr16(acc);
    int ci = pipe_s32(0, 10, 16, g_wmsg, s_Wb, s_ea, SEA, acc, tid, lrow, lcol8, mr0);
#pragma unroll
    for (int nt = 0; nt < 16; nt++) {
        int col = 8 * nt + 2 * c;
        float b0 = s_bias[col], b1v = s_bias[col + 1];
        aP[2 * nt]     = packbf(siluf(acc[nt][0] + b0), siluf(acc[nt][1] + b1v));
        aP[2 * nt + 1] = packbf(siluf(acc[nt][2] + b0), siluf(acc[nt][3] + b1v));
    }
    // fc2 (chunks 1-4), A from regs
    clr16(acc);
    ci = pipe_r(ci, 4, 10, 16, g_wmsg, s_Wb, aP, acc, tid, lrow, lcol8);
#pragma unroll
    for (int nt = 0; nt < 16; nt++) {
        int col = 8 * nt + 2 * c;
        float b0 = s_bias[128 + col], b1v = s_bias[128 + col + 1];
        aP[2 * nt]     = packbf(siluf(acc[nt][0] + b0), siluf(acc[nt][1] + b1v));
        aP[2 * nt + 1] = packbf(siluf(acc[nt][2] + b0), siluf(acc[nt][3] + b1v));
    }
    // fc3 (chunks 5-8), A from regs -> scale (fp32 in acc)
    clr16(acc);
    ci = pipe_r(ci, 4, 10, 16, g_wmsg, s_Wb, aP, acc, tid, lrow, lcol8);
#pragma unroll
    for (int nt = 0; nt < 16; nt++) {
        int col = 8 * nt + 2 * c;
        acc[nt][0] += s_bias[256 + col];
        acc[nt][1] += s_bias[256 + col + 1];
        acc[nt][2] += s_bias[256 + col];
        acc[nt][3] += s_bias[256 + col + 1];
    }
    // prod = xw * scale -> bf16 back into s_x (frag-owned slots; disjoint cols per step)
#pragma unroll
    for (int ks = 0; ks < 8; ks++) {
        unsigned xw[4];
        ldsm4(xw, cvta(s_x + (mr0 + lrow) * XS + 16 * ks + lcol8));
        float2 f;
        f = __bfloat1622float2(*(__nv_bfloat162*)&xw[0]);
        *(unsigned*)(s_x + (mr0 + r) * XS + 16 * ks + 2 * c) =
            packbf(f.x * acc[2 * ks][0], f.y * acc[2 * ks][1]);
        f = __bfloat1622float2(*(__nv_bfloat162*)&xw[1]);
        *(unsigned*)(s_x + (mr0 + r + 8) * XS + 16 * ks + 2 * c) =
            packbf(f.x * acc[2 * ks][2], f.y * acc[2 * ks][3]);
        f = __bfloat1622float2(*(__nv_bfloat162*)&xw[2]);
        *(unsigned*)(s_x + (mr0 + r) * XS + 16 * ks + 8 + 2 * c) =
            packbf(f.x * acc[2 * ks + 1][0], f.y * acc[2 * ks + 1][1]);
        f = __bfloat1622float2(*(__nv_bfloat162*)&xw[3]);
        *(unsigned*)(s_x + (mr0 + r + 8) * XS + 16 * ks + 8 + 2 * c) =
            packbf(f.x * acc[2 * ks + 1][2], f.y * acc[2 * ks + 1][3]);
    }
    // shp = edge_sh @ W_sh (chunk 9, 16 rows, A = s_sh)
    clr16(acc);
    commit_empty();
    wait1();
    __syncthreads();
    cmma_s<16>(s_Wb + (ci & 1) * CHUNKW, s_sh, SSH, acc, lrow, lcol8, mr0);
    // msg = silu(prod + shp) * wt -> s_x
    float w0 = s_wt[mr0 + r], w1 = s_wt[mr0 + r + 8];
#pragma unroll
    for (int nt = 0; nt < 16; nt++) {
        int col = 8 * nt + 2 * c;
        float2 p0 = __bfloat1622float2(*(__nv_bfloat162*)(s_x + (mr0 + r) * XS + col));
        float2 p1 = __bfloat1622float2(*(__nv_bfloat162*)(s_x + (mr0 + r + 8) * XS + col));
        *(unsigned*)(s_x + (mr0 + r) * XS + col) =
            packbf(siluf(p0.x + acc[nt][0]) * w0, siluf(p0.y + acc[nt][1]) * w0);
        *(unsigned*)(s_x + (mr0 + r + 8) * XS + col) =
            packbf(siluf(p1.x + acc[nt][2]) * w1, siluf(p1.y + acc[nt][3]) * w1);
    }
    __syncwarp();
    // scatter: 16 warp-private rows
#pragma unroll
    for (int i = 0; i < 16; i++) {
        int rr = mr0 + i;
        int d = s_dst[rr];
        __nv_bfloat162 p0 = *(__nv_bfloat162*)(s_x + rr * XS + lane * 4);
        __nv_bfloat162 p1 = *(__nv_bfloat162*)(s_x + rr * XS + lane * 4 + 2);
        float2 f0 = __bfloat1622float2(p0), f1 = __bfloat1622float2(p1);
        float* p = g_agg + (size_t)d * DD + lane * 4;
        atomicAdd(p + 0, f0.x);
        atomicAdd(p + 1, f0.y);
        atomicAdd(p + 2, f1.x);
        atomicAdd(p + 3, f1.y);
    }
}

// ---------------- K4: out = LN(nf + agg @ W_out) ----------------
__global__ void k_node(const float* __restrict__ nf, const float* __restrict__ W_out,
                       float* __restrict__ out)
{
    extern __shared__ float smemf[];
    float* sW    = smemf;
    float* s_row = sW + 128 * 128;
    const int tid = threadIdx.x, tx = tid & 31, w = tid >> 5;
    for (int idx = tid; idx < 128 * 32; idx += 256) {
        int rr = idx >> 5, cc = (idx & 31) << 2;
        *(float4*)(sW + rr * 128 + cc) = *(const float4*)(W_out + (size_t)rr * 128 + cc);
    }
    __syncthreads();
    for (int n = blockIdx.x * 8 + w; n < NN; n += gridDim.x * 8) {
        float4 av = *(const float4*)(g_agg + (size_t)n * DD + tx * 4);
        __syncwarp();
        *(float4*)(s_row + w * 128 + tx * 4) = av;
        __syncwarp();
        float a0 = 0.f, a1 = 0.f, a2 = 0.f, a3 = 0.f;
#pragma unroll 8
        for (int k = 0; k < 128; k++) {
            float a = s_row[w * 128 + k];
            const float4 wv = *(const float4*)(sW + k * 128 + tx * 4);
            a0 += a * wv.x; a1 += a * wv.y; a2 += a * wv.z; a3 += a * wv.w;
        }
        const float4 x = *(const float4*)(nf + (size_t)n * DD + tx * 4);
        float v0 = x.x + a0, v1 = x.y + a1, v2 = x.z + a2, v3 = x.w + a3;
        float s = v0 + v1 + v2 + v3;
#pragma unroll
        for (int o = 16; o > 0; o >>= 1) s += __shfl_xor_sync(0xffffffffu, s, o);
        float mu = s * (1.f / 128.f);
        float d0 = v0 - mu, d1 = v1 - mu, d2 = v2 - mu, d3 = v3 - mu;
        float q = d0 * d0 + d1 * d1 + d2 * d2 + d3 * d3;
#pragma unroll
        for (int o = 16; o > 0; o >>= 1) q += __shfl_xor_sync(0xffffffffu, q, o);
        float rs = rsqrtf(q * (1.f / 128.f) + 1e-5f);
        float4 o4 = make_float4(d0 * rs, d1 * rs, d2 * rs, d3 * rs);
        *(float4*)(out + (size_t)n * DD + tx * 4) = o4;
    }
}

extern "C" void kernel_launch(void* const* d_in, const int* in_sizes, int n_in,
                              void* d_out, int out_size)
{
    const float* nf        = (const float*)d_in[0];
    const float* edge_attr = (const float*)d_in[1];
    const float* edge_sh   = (const float*)d_in[2];
    const float* W_node    = (const float*)d_in[3];
    const float* fc1 = (const float*)d_in[4];
    const float* b1  = (const float*)d_in[5];
    const float* fc2 = (const float*)d_in[6];
    const float* b2  = (const float*)d_in[7];
    const float* fc3 = (const float*)d_in[8];
    const float* b3  = (const float*)d_in[9];
    const float* W_sh = (const float*)d_in[10];
    const float* aW1 = (const float*)d_in[11];
    const float* ab1 = (const float*)d_in[12];
    const float* aW2 = (const float*)d_in[13];
    const float* ab2 = (const float*)d_in[14];
    const float* aW3 = (const float*)d_in[15];
    const float* ab3 = (const float*)d_in[16];
    const float* W_out = (const float*)d_in[17];
    const int* edge_index = (const int*)d_in[18];
    float* out = (float*)d_out;

    const int SMEM_NP   = 38912;
    const int SMEM_ATT  = 43552;
    const int SMEM_MSG  = 45344;
    const int SMEM_NODE = (128 * 128 + 8 * 128) * 4;
    cudaFuncSetAttribute(k_nodeproj, cudaFuncAttributeMaxDynamicSharedMemorySize, SMEM_NP);
    cudaFuncSetAttribute(k_att,  cudaFuncAttributeMaxDynamicSharedMemorySize, SMEM_ATT);
    cudaFuncSetAttribute(k_msg,  cudaFuncAttributeMaxDynamicSharedMemorySize, SMEM_MSG);
    cudaFuncSetAttribute(k_node, cudaFuncAttributeMaxDynamicSharedMemorySize, SMEM_NODE);

    k_prep<<<152, 256>>>(W_node, fc1, fc2, fc3, W_sh, aW1, aW2, aW3);
    k_init<<<2048, 256>>>();
    k_nodeproj<<<(NN + 63) / 64, 256, SMEM_NP>>>(nf);
    k_att<<<EE / TE, 128, SMEM_ATT>>>(edge_attr, ab1, ab2, ab3, edge_index);
    k_sumexp<<<1024, 256>>>();
    k_msg<<<EE / TE, 128, SMEM_MSG>>>(edge_attr, edge_sh, b1, b2, b3, edge_index);
    k_node<<<296, 256, SMEM_NODE>>>(nf, W_out, out);
}